// round 2
// baseline (speedup 1.0000x reference)
#include <cuda_runtime.h>
#include <math.h>

// Problem constants
#define BATCH   16
#define SEQ     1024
#define EMB     1024
#define NHEAD   16
#define DK      64
#define MROWS   (BATCH * SEQ)        // 16384

// Scratch (device globals; no allocation allowed)
__device__ float g_q[BATCH * NHEAD * SEQ * DK];     // [B,H,N,dk]
__device__ float g_k[BATCH * NHEAD * SEQ * DK];
__device__ float g_v[BATCH * NHEAD * SEQ * DK];
__device__ float g_ctx[BATCH * SEQ * EMB];          // [B,N,D]

// ---------------------------------------------------------------------------
// Kernel 1: QKV GEMM.  A[16384,1024] @ W[1024,3072] + bias -> scatter to Q/K/V
// 128x128 block tile, BK=8, 256 threads, 8x8 per-thread micro tile.
// ---------------------------------------------------------------------------
__global__ __launch_bounds__(256) void qkv_gemm(const float* __restrict__ A,
                                                const float* __restrict__ W,
                                                const float* __restrict__ bias) {
    __shared__ float As[8][128];   // As[k][m]
    __shared__ float Bs[8][128];   // Bs[k][n]

    const int t = threadIdx.x;
    const int mBase = blockIdx.y * 128;
    const int nBase = blockIdx.x * 128;
    const int row0 = (t >> 4) << 3;   // 0..120
    const int col0 = (t & 15) << 3;

    const int aRow = t >> 1;          // 0..127
    const int aK   = (t & 1) << 2;    // 0 or 4
    const int bRow = t >> 5;          // 0..7
    const int bCol = (t & 31) << 2;   // 0..124

    const float* Aptr = A + (size_t)(mBase + aRow) * 1024 + aK;
    const float* Wptr = W + (size_t)bRow * 3072 + nBase + bCol;

    float acc[8][8];
#pragma unroll
    for (int i = 0; i < 8; i++)
#pragma unroll
        for (int j = 0; j < 8; j++) acc[i][j] = 0.f;

    for (int k0 = 0; k0 < 1024; k0 += 8) {
        float4 av = *(const float4*)(Aptr + k0);
        float4 wv = *(const float4*)(Wptr + (size_t)k0 * 3072);
        As[aK + 0][aRow] = av.x;
        As[aK + 1][aRow] = av.y;
        As[aK + 2][aRow] = av.z;
        As[aK + 3][aRow] = av.w;
        *(float4*)&Bs[bRow][bCol] = wv;
        __syncthreads();

#pragma unroll
        for (int kk = 0; kk < 8; kk++) {
            float ra[8], rb[8];
            *(float4*)(ra)     = *(const float4*)&As[kk][row0];
            *(float4*)(ra + 4) = *(const float4*)&As[kk][row0 + 4];
            *(float4*)(rb)     = *(const float4*)&Bs[kk][col0];
            *(float4*)(rb + 4) = *(const float4*)&Bs[kk][col0 + 4];
#pragma unroll
            for (int i = 0; i < 8; i++)
#pragma unroll
                for (int j = 0; j < 8; j++) acc[i][j] += ra[i] * rb[j];
        }
        __syncthreads();
    }

    // Epilogue: add bias, scatter into Q/K/V as [B,H,N,dk]
#pragma unroll
    for (int i = 0; i < 8; i++) {
        int m = mBase + row0 + i;
        int b = m >> 10;
        int n = m & 1023;
#pragma unroll
        for (int j = 0; j < 8; j++) {
            int c = nBase + col0 + j;
            float v = acc[i][j] + __ldg(&bias[c]);
            int which = c >> 10;
            int h = (c >> 6) & 15;
            int d = c & 63;
            size_t idx = ((size_t)(b * NHEAD + h) * SEQ + n) * DK + d;
            if (which == 0)      g_q[idx] = v;
            else if (which == 1) g_k[idx] = v;
            else                 g_v[idx] = v;
        }
    }
}

// ---------------------------------------------------------------------------
// Kernel 2: flash attention.  One block per (q-tile of 64, b*h).
// 256 threads, 4x4 micro tiles, online softmax, P staged via smem.
// ---------------------------------------------------------------------------
__global__ __launch_bounds__(256) void flash_attn() {
    extern __shared__ float sm[];
    float* Qt = sm;              // [64][64]  Qt[d][i]
    float* Kt = sm + 4096;       // [64][64]  Kt[d][j]
    float* Vs = sm + 8192;       // [64][64]  Vs[j][c]
    float* Ps = sm + 12288;      // [64][65]  Ps[i][j]

    const int t  = threadIdx.x;
    const int ty = t >> 4;       // 0..15 -> q rows ty*4..
    const int tx = t & 15;       // 0..15 -> cols  tx*4..
    const int qtile = blockIdx.x;
    const int bh    = blockIdx.y;

    const float* Qg = g_q + ((size_t)bh * SEQ + qtile * 64) * DK;
    const float* Kg = g_k + (size_t)bh * SEQ * DK;
    const float* Vg = g_v + (size_t)bh * SEQ * DK;

    const float scale = 0.125f;  // 1/sqrt(64)

    // Load Q tile transposed (and pre-scaled): Qt[d][i]
#pragma unroll
    for (int i2 = 0; i2 < 4; i2++) {
        int e  = t + (i2 << 8);       // float4 index 0..1023
        int r  = e >> 4;              // q row 0..63
        int c4 = (e & 15) << 2;       // d 0..60
        float4 v = *(const float4*)(Qg + r * 64 + c4);
        Qt[(c4 + 0) * 64 + r] = v.x * scale;
        Qt[(c4 + 1) * 64 + r] = v.y * scale;
        Qt[(c4 + 2) * 64 + r] = v.z * scale;
        Qt[(c4 + 3) * 64 + r] = v.w * scale;
    }

    float o[4][4];
    float rm[4], rl[4];
#pragma unroll
    for (int r = 0; r < 4; r++) {
        rm[r] = -INFINITY;
        rl[r] = 0.f;
#pragma unroll
        for (int c = 0; c < 4; c++) o[r][c] = 0.f;
    }

    for (int kt = 0; kt < 16; kt++) {
        __syncthreads();  // previous-tile smem reads done (also covers Q store)

        // Load K transposed, V natural
#pragma unroll
        for (int i2 = 0; i2 < 4; i2++) {
            int e  = t + (i2 << 8);
            int r  = e >> 4;
            int c4 = (e & 15) << 2;
            float4 kv = *(const float4*)(Kg + (size_t)kt * 64 * 64 + r * 64 + c4);
            Kt[(c4 + 0) * 64 + r] = kv.x;
            Kt[(c4 + 1) * 64 + r] = kv.y;
            Kt[(c4 + 2) * 64 + r] = kv.z;
            Kt[(c4 + 3) * 64 + r] = kv.w;
            float4 vv = *(const float4*)(Vg + (size_t)kt * 64 * 64 + r * 64 + c4);
            *(float4*)&Vs[r * 64 + c4] = vv;
        }
        __syncthreads();

        // S = (Q*scale) K^T  (4x4 per thread)
        float s[4][4];
#pragma unroll
        for (int r = 0; r < 4; r++)
#pragma unroll
            for (int c = 0; c < 4; c++) s[r][c] = 0.f;

#pragma unroll 8
        for (int d = 0; d < 64; d++) {
            float4 q = *(const float4*)&Qt[d * 64 + ty * 4];
            float4 k = *(const float4*)&Kt[d * 64 + tx * 4];
            float qa[4] = {q.x, q.y, q.z, q.w};
            float ka[4] = {k.x, k.y, k.z, k.w};
#pragma unroll
            for (int r = 0; r < 4; r++)
#pragma unroll
                for (int c = 0; c < 4; c++) s[r][c] += qa[r] * ka[c];
        }

        // Online softmax per q-row (rows owned by 16-lane tx groups)
#pragma unroll
        for (int r = 0; r < 4; r++) {
            float mx = fmaxf(fmaxf(s[r][0], s[r][1]), fmaxf(s[r][2], s[r][3]));
#pragma unroll
            for (int w = 1; w < 16; w <<= 1)
                mx = fmaxf(mx, __shfl_xor_sync(0xffffffffu, mx, w, 16));
            float mnew  = fmaxf(rm[r], mx);
            float alpha = __expf(rm[r] - mnew);
            float sum = 0.f;
#pragma unroll
            for (int c = 0; c < 4; c++) {
                s[r][c] = __expf(s[r][c] - mnew);
                sum += s[r][c];
            }
#pragma unroll
            for (int w = 1; w < 16; w <<= 1)
                sum += __shfl_xor_sync(0xffffffffu, sum, w, 16);
            rl[r] = rl[r] * alpha + sum;
            rm[r] = mnew;
#pragma unroll
            for (int c = 0; c < 4; c++) o[r][c] *= alpha;
            // stage P: Ps[i][j]
#pragma unroll
            for (int c = 0; c < 4; c++)
                Ps[(ty * 4 + r) * 65 + tx * 4 + c] = s[r][c];
        }
        __syncthreads();

        // O += P @ V
#pragma unroll 8
        for (int j = 0; j < 64; j++) {
            float p[4];
#pragma unroll
            for (int r = 0; r < 4; r++) p[r] = Ps[(ty * 4 + r) * 65 + j];
            float4 v = *(const float4*)&Vs[j * 64 + tx * 4];
            float va[4] = {v.x, v.y, v.z, v.w};
#pragma unroll
            for (int r = 0; r < 4; r++)
#pragma unroll
                for (int c = 0; c < 4; c++) o[r][c] += p[r] * va[c];
        }
    }

    // Normalize + write context as [B,N,D] with D index = h*64 + c
    const int h = bh & 15;
    const int b = bh >> 4;
#pragma unroll
    for (int r = 0; r < 4; r++) {
        float inv = 1.0f / rl[r];
        int n = qtile * 64 + ty * 4 + r;
        float4 ov;
        ov.x = o[r][0] * inv;
        ov.y = o[r][1] * inv;
        ov.z = o[r][2] * inv;
        ov.w = o[r][3] * inv;
        size_t base = ((size_t)b * SEQ + n) * EMB + h * 64 + tx * 4;
        *(float4*)&g_ctx[base] = ov;
    }
}

// ---------------------------------------------------------------------------
// Kernel 3: FC GEMM.  ctx[16384,1024] @ W_fc[1024,1024] + b_fc -> out
// ---------------------------------------------------------------------------
__global__ __launch_bounds__(256) void fc_gemm(const float* __restrict__ W,
                                               const float* __restrict__ bias,
                                               float* __restrict__ out) {
    __shared__ float As[8][128];
    __shared__ float Bs[8][128];

    const int t = threadIdx.x;
    const int mBase = blockIdx.y * 128;
    const int nBase = blockIdx.x * 128;
    const int row0 = (t >> 4) << 3;
    const int col0 = (t & 15) << 3;

    const int aRow = t >> 1;
    const int aK   = (t & 1) << 2;
    const int bRow = t >> 5;
    const int bCol = (t & 31) << 2;

    const float* Aptr = g_ctx + (size_t)(mBase + aRow) * 1024 + aK;
    const float* Wptr = W + (size_t)bRow * 1024 + nBase + bCol;

    float acc[8][8];
#pragma unroll
    for (int i = 0; i < 8; i++)
#pragma unroll
        for (int j = 0; j < 8; j++) acc[i][j] = 0.f;

    for (int k0 = 0; k0 < 1024; k0 += 8) {
        float4 av = *(const float4*)(Aptr + k0);
        float4 wv = *(const float4*)(Wptr + (size_t)k0 * 1024);
        As[aK + 0][aRow] = av.x;
        As[aK + 1][aRow] = av.y;
        As[aK + 2][aRow] = av.z;
        As[aK + 3][aRow] = av.w;
        *(float4*)&Bs[bRow][bCol] = wv;
        __syncthreads();

#pragma unroll
        for (int kk = 0; kk < 8; kk++) {
            float ra[8], rb[8];
            *(float4*)(ra)     = *(const float4*)&As[kk][row0];
            *(float4*)(ra + 4) = *(const float4*)&As[kk][row0 + 4];
            *(float4*)(rb)     = *(const float4*)&Bs[kk][col0];
            *(float4*)(rb + 4) = *(const float4*)&Bs[kk][col0 + 4];
#pragma unroll
            for (int i = 0; i < 8; i++)
#pragma unroll
                for (int j = 0; j < 8; j++) acc[i][j] += ra[i] * rb[j];
        }
        __syncthreads();
    }

#pragma unroll
    for (int i = 0; i < 8; i++) {
        int m = mBase + row0 + i;
#pragma unroll
        for (int j = 0; j < 8; j += 4) {
            int c = nBase + col0 + j;
            float4 ov;
            ov.x = acc[i][j + 0] + __ldg(&bias[c + 0]);
            ov.y = acc[i][j + 1] + __ldg(&bias[c + 1]);
            ov.z = acc[i][j + 2] + __ldg(&bias[c + 2]);
            ov.w = acc[i][j + 3] + __ldg(&bias[c + 3]);
            *(float4*)&out[(size_t)m * 1024 + c] = ov;
        }
    }
}

// ---------------------------------------------------------------------------
extern "C" void kernel_launch(void* const* d_in, const int* in_sizes, int n_in,
                              void* d_out, int out_size) {
    (void)in_sizes; (void)n_in; (void)out_size;
    const float* x     = (const float*)d_in[0];
    const float* W_qkv = (const float*)d_in[1];
    const float* b_qkv = (const float*)d_in[2];
    const float* W_fc  = (const float*)d_in[3];
    const float* b_fc  = (const float*)d_in[4];
    float* out = (float*)d_out;

    // QKV projection: [16384,1024] @ [1024,3072]
    {
        dim3 grid(3072 / 128, MROWS / 128);
        qkv_gemm<<<grid, 256>>>(x, W_qkv, b_qkv);
    }

    // Flash attention: 16 q-tiles x 256 (b,h)
    {
        int smem = (3 * 64 * 64 + 64 * 65) * (int)sizeof(float);  // 65792 B
        cudaFuncSetAttribute(flash_attn, cudaFuncAttributeMaxDynamicSharedMemorySize, smem);
        dim3 grid(SEQ / 64, BATCH * NHEAD);
        flash_attn<<<grid, 256, smem>>>();
    }

    // Output projection: [16384,1024] @ [1024,1024]
    {
        dim3 grid(1024 / 128, MROWS / 128);
        fc_gemm<<<grid, 256>>>(W_fc, b_fc, out);
    }
}

// round 5
// speedup vs baseline: 1.5926x; 1.5926x over previous
#include <cuda_runtime.h>
#include <cuda_bf16.h>
#include <math.h>
#include <stdint.h>

// Problem constants
#define BATCH   16
#define SEQ     1024
#define EMB     1024
#define NHEAD   16
#define DK      64
#define MROWS   (BATCH * SEQ)        // 16384

// Scratch (device globals; no allocation allowed)
__device__ float g_q[BATCH * NHEAD * SEQ * DK];     // [B,H,N,dk]
__device__ float g_k[BATCH * NHEAD * SEQ * DK];
__device__ float g_v[BATCH * NHEAD * SEQ * DK];
__device__ float g_ctx[BATCH * SEQ * EMB];          // [B,N,D]

// ---------------------------------------------------------------------------
// mma.sync helpers (legacy tensor-core path; valid on plain sm_103 target)
// ---------------------------------------------------------------------------
__device__ __forceinline__ uint32_t sm_u32(const void* p) {
    uint32_t a;
    asm("{ .reg .u64 t; cvta.to.shared.u64 t, %1; cvt.u32.u64 %0, t; }"
        : "=r"(a) : "l"(p));
    return a;
}

__device__ __forceinline__ void ldsm4(uint32_t addr, uint32_t* r) {
    asm volatile("ldmatrix.sync.aligned.m8n8.x4.shared.b16 {%0,%1,%2,%3}, [%4];"
                 : "=r"(r[0]), "=r"(r[1]), "=r"(r[2]), "=r"(r[3]) : "r"(addr));
}
__device__ __forceinline__ void ldsm4t(uint32_t addr, uint32_t* r) {
    asm volatile("ldmatrix.sync.aligned.m8n8.x4.trans.shared.b16 {%0,%1,%2,%3}, [%4];"
                 : "=r"(r[0]), "=r"(r[1]), "=r"(r[2]), "=r"(r[3]) : "r"(addr));
}
__device__ __forceinline__ void mma16816(float* d, const uint32_t* a, const uint32_t* b) {
    asm volatile(
        "mma.sync.aligned.m16n8k16.row.col.f32.bf16.bf16.f32 "
        "{%0,%1,%2,%3}, {%4,%5,%6,%7}, {%8,%9}, {%0,%1,%2,%3};"
        : "+f"(d[0]), "+f"(d[1]), "+f"(d[2]), "+f"(d[3])
        : "r"(a[0]), "r"(a[1]), "r"(a[2]), "r"(a[3]), "r"(b[0]), "r"(b[1]));
}

// smem geometry (bytes)
#define A_PITCH 80              // [m][k] rows, 32 k * 2B = 64 data + 16 pad
#define B_PITCH 272             // [k][n] rows, 128 n * 2B = 256 data + 16 pad
#define AH_OFF  0
#define AL_OFF  (128 * A_PITCH)                 // 10240
#define BH_OFF  (2 * 128 * A_PITCH)             // 20480
#define BL_OFF  (BH_OFF + 32 * B_PITCH)         // 29184
#define BUF_SZ  (BL_OFF + 32 * B_PITCH)         // 37888
#define GSM_TOTAL (2 * BUF_SZ)                  // 75776

// ---------------------------------------------------------------------------
// bf16-split tensor GEMM:  out[16384, N] = A[16384,1024] @ W[1024,N] + bias
// MODE 0: N=3072, A from arg, scatter to g_q/g_k/g_v.
// MODE 1: N=1024, A = g_ctx (device symbol, resolved in device code!), out arg.
// ---------------------------------------------------------------------------
template <int MODE>
__global__ __launch_bounds__(256) void gemm_mma(const float* __restrict__ A_in,
                                                const float* __restrict__ W,
                                                const float* __restrict__ bias,
                                                float* __restrict__ out,
                                                int ldW) {
    extern __shared__ char smem[];
    const uint32_t smb = sm_u32(smem);
    const int tid  = threadIdx.x;
    const int lane = tid & 31;
    const int wid  = tid >> 5;
    const int wm   = wid & 3;          // m block of 32
    const int wn   = wid >> 2;         // n block of 64
    const int mBase = blockIdx.y * 128;
    const int nBase = blockIdx.x * 128;

    // CRITICAL: device symbols must be resolved in device code, not host.
    const float* A = (MODE == 1) ? (const float*)g_ctx : A_in;

    // accumulators: [mt 2][nt 8][4]
    float acc[2][8][4];
#pragma unroll
    for (int i = 0; i < 2; i++)
#pragma unroll
        for (int j = 0; j < 8; j++)
#pragma unroll
            for (int q = 0; q < 4; q++) acc[i][j][q] = 0.f;

    // staging regs
    float4 ra[4], rb[4];

    // gmem load helper indices
    const int am = tid >> 3;           // + i*32 -> m row
    const int aq = tid & 7;            // k-quad
    const int bk = tid >> 5;           // + i*8 -> k row
    const int bq = tid & 31;           // n-quad

    // ---- prologue: load + store chunk 0 ----
#pragma unroll
    for (int i = 0; i < 4; i++) {
        ra[i] = __ldg((const float4*)(A + (size_t)(mBase + am + i * 32) * 1024 + aq * 4));
        rb[i] = __ldg((const float4*)(W + (size_t)(bk + i * 8) * ldW + nBase + bq * 4));
    }

    auto sts_chunk = [&](int buf) {
        char* base = smem + buf * BUF_SZ;
#pragma unroll
        for (int i = 0; i < 4; i++) {
            // A -> [m][k] pitch 80
            float4 v = ra[i];
            __nv_bfloat162 h01 = __floats2bfloat162_rn(v.x, v.y);
            __nv_bfloat162 h23 = __floats2bfloat162_rn(v.z, v.w);
            __nv_bfloat162 l01 = __floats2bfloat162_rn(v.x - __bfloat162float(h01.x),
                                                       v.y - __bfloat162float(h01.y));
            __nv_bfloat162 l23 = __floats2bfloat162_rn(v.z - __bfloat162float(h23.x),
                                                       v.w - __bfloat162float(h23.y));
            int off = (am + i * 32) * A_PITCH + aq * 8;
            *(uint2*)(base + AH_OFF + off) = make_uint2(*(uint32_t*)&h01, *(uint32_t*)&h23);
            *(uint2*)(base + AL_OFF + off) = make_uint2(*(uint32_t*)&l01, *(uint32_t*)&l23);
            // B -> [k][n] pitch 272
            float4 w = rb[i];
            __nv_bfloat162 bh01 = __floats2bfloat162_rn(w.x, w.y);
            __nv_bfloat162 bh23 = __floats2bfloat162_rn(w.z, w.w);
            __nv_bfloat162 bl01 = __floats2bfloat162_rn(w.x - __bfloat162float(bh01.x),
                                                        w.y - __bfloat162float(bh01.y));
            __nv_bfloat162 bl23 = __floats2bfloat162_rn(w.z - __bfloat162float(bh23.x),
                                                        w.w - __bfloat162float(bh23.y));
            int boff = (bk + i * 8) * B_PITCH + bq * 8;
            *(uint2*)(base + BH_OFF + boff) = make_uint2(*(uint32_t*)&bh01, *(uint32_t*)&bh23);
            *(uint2*)(base + BL_OFF + boff) = make_uint2(*(uint32_t*)&bl01, *(uint32_t*)&bl23);
        }
    };

    sts_chunk(0);
    __syncthreads();

    for (int c = 0; c < 32; c++) {
        const int buf = c & 1;

        // issue gmem loads for next chunk (overlap with mma)
        if (c + 1 < 32) {
            const int kOff = (c + 1) * 32;
#pragma unroll
            for (int i = 0; i < 4; i++) {
                ra[i] = __ldg((const float4*)(A + (size_t)(mBase + am + i * 32) * 1024 + kOff + aq * 4));
                rb[i] = __ldg((const float4*)(W + (size_t)(kOff + bk + i * 8) * ldW + nBase + bq * 4));
            }
        }

        // ---- compute from smem buffer ----
        const uint32_t sb = smb + buf * BUF_SZ;
#pragma unroll
        for (int ks = 0; ks < 2; ks++) {
            const int k0 = ks * 16;
            uint32_t Ah[2][4], Al[2][4], Bh[8][2], Bl[8][2];
#pragma unroll
            for (int mt = 0; mt < 2; mt++) {
                uint32_t addr = sb + (uint32_t)((wm * 32 + mt * 16 + (lane & 15)) * A_PITCH
                                                + (k0 + (lane >> 4) * 8) * 2);
                ldsm4(addr + AH_OFF, Ah[mt]);
                ldsm4(addr + AL_OFF, Al[mt]);
            }
#pragma unroll
            for (int p = 0; p < 4; p++) {
                uint32_t addr = sb + (uint32_t)((k0 + (lane & 15)) * B_PITCH
                                                + (wn * 64 + p * 16 + (lane >> 4) * 8) * 2);
                uint32_t r[4];
                ldsm4t(addr + BH_OFF, r);
                Bh[2 * p][0] = r[0]; Bh[2 * p][1] = r[1];
                Bh[2 * p + 1][0] = r[2]; Bh[2 * p + 1][1] = r[3];
                ldsm4t(addr + BL_OFF, r);
                Bl[2 * p][0] = r[0]; Bl[2 * p][1] = r[1];
                Bl[2 * p + 1][0] = r[2]; Bl[2 * p + 1][1] = r[3];
            }
            // hi*hi
#pragma unroll
            for (int mt = 0; mt < 2; mt++)
#pragma unroll
                for (int nt = 0; nt < 8; nt++) mma16816(acc[mt][nt], Ah[mt], Bh[nt]);
            // hi*lo
#pragma unroll
            for (int mt = 0; mt < 2; mt++)
#pragma unroll
                for (int nt = 0; nt < 8; nt++) mma16816(acc[mt][nt], Ah[mt], Bl[nt]);
            // lo*hi
#pragma unroll
            for (int mt = 0; mt < 2; mt++)
#pragma unroll
                for (int nt = 0; nt < 8; nt++) mma16816(acc[mt][nt], Al[mt], Bh[nt]);
        }
        __syncthreads();

        if (c + 1 < 32) {
            sts_chunk((c + 1) & 1);
            __syncthreads();
        }
    }

    // ---- epilogue ----
    const int rbase = mBase + wm * 32 + (lane >> 2);
    const int cbase = nBase + wn * 64 + 2 * (lane & 3);
#pragma unroll
    for (int mt = 0; mt < 2; mt++) {
#pragma unroll
        for (int nt = 0; nt < 8; nt++) {
            const int col = cbase + nt * 8;
            const float bx = __ldg(&bias[col]);
            const float by = __ldg(&bias[col + 1]);
#pragma unroll
            for (int half = 0; half < 2; half++) {
                const int row = rbase + mt * 16 + half * 8;
                float2 ov;
                ov.x = acc[mt][nt][half * 2 + 0] + bx;
                ov.y = acc[mt][nt][half * 2 + 1] + by;
                if (MODE == 1) {
                    *(float2*)(out + (size_t)row * 1024 + col) = ov;
                } else {
                    const int which = col >> 10;
                    const int h = (col >> 6) & 15;
                    const int d0 = col & 63;
                    const int b = row >> 10;
                    const int n_tok = row & 1023;
                    float* dst = (which == 0) ? g_q : (which == 1) ? g_k : g_v;
                    *(float2*)(dst + ((size_t)(b * NHEAD + h) * SEQ + n_tok) * DK + d0) = ov;
                }
            }
        }
    }
}

// ---------------------------------------------------------------------------
// Kernel 2: flash attention (fp32).  One block per (q-tile 64, b*h).
// ---------------------------------------------------------------------------
__global__ __launch_bounds__(256) void flash_attn() {
    extern __shared__ float sm[];
    float* Qt = sm;              // [64][64]  Qt[d][i]
    float* Kt = sm + 4096;       // [64][64]  Kt[d][j]
    float* Vs = sm + 8192;       // [64][64]  Vs[j][c]
    float* Ps = sm + 12288;      // [64][65]  Ps[i][j]

    const int t  = threadIdx.x;
    const int ty = t >> 4;
    const int tx = t & 15;
    const int qtile = blockIdx.x;
    const int bh    = blockIdx.y;

    const float* Qg = g_q + ((size_t)bh * SEQ + qtile * 64) * DK;
    const float* Kg = g_k + (size_t)bh * SEQ * DK;
    const float* Vg = g_v + (size_t)bh * SEQ * DK;

    const float scale = 0.125f;

#pragma unroll
    for (int i2 = 0; i2 < 4; i2++) {
        int e  = t + (i2 << 8);
        int r  = e >> 4;
        int c4 = (e & 15) << 2;
        float4 v = *(const float4*)(Qg + r * 64 + c4);
        Qt[(c4 + 0) * 64 + r] = v.x * scale;
        Qt[(c4 + 1) * 64 + r] = v.y * scale;
        Qt[(c4 + 2) * 64 + r] = v.z * scale;
        Qt[(c4 + 3) * 64 + r] = v.w * scale;
    }

    float o[4][4];
    float rm[4], rl[4];
#pragma unroll
    for (int r = 0; r < 4; r++) {
        rm[r] = -INFINITY;
        rl[r] = 0.f;
#pragma unroll
        for (int c = 0; c < 4; c++) o[r][c] = 0.f;
    }

    for (int kt = 0; kt < 16; kt++) {
        __syncthreads();
#pragma unroll
        for (int i2 = 0; i2 < 4; i2++) {
            int e  = t + (i2 << 8);
            int r  = e >> 4;
            int c4 = (e & 15) << 2;
            float4 kv = *(const float4*)(Kg + (size_t)kt * 64 * 64 + r * 64 + c4);
            Kt[(c4 + 0) * 64 + r] = kv.x;
            Kt[(c4 + 1) * 64 + r] = kv.y;
            Kt[(c4 + 2) * 64 + r] = kv.z;
            Kt[(c4 + 3) * 64 + r] = kv.w;
            float4 vv = *(const float4*)(Vg + (size_t)kt * 64 * 64 + r * 64 + c4);
            *(float4*)&Vs[r * 64 + c4] = vv;
        }
        __syncthreads();

        float s[4][4];
#pragma unroll
        for (int r = 0; r < 4; r++)
#pragma unroll
            for (int c = 0; c < 4; c++) s[r][c] = 0.f;

#pragma unroll 8
        for (int d = 0; d < 64; d++) {
            float4 q = *(const float4*)&Qt[d * 64 + ty * 4];
            float4 k = *(const float4*)&Kt[d * 64 + tx * 4];
            float qa[4] = {q.x, q.y, q.z, q.w};
            float ka[4] = {k.x, k.y, k.z, k.w};
#pragma unroll
            for (int r = 0; r < 4; r++)
#pragma unroll
                for (int c = 0; c < 4; c++) s[r][c] += qa[r] * ka[c];
        }

#pragma unroll
        for (int r = 0; r < 4; r++) {
            float mx = fmaxf(fmaxf(s[r][0], s[r][1]), fmaxf(s[r][2], s[r][3]));
#pragma unroll
            for (int w = 1; w < 16; w <<= 1)
                mx = fmaxf(mx, __shfl_xor_sync(0xffffffffu, mx, w, 16));
            float mnew  = fmaxf(rm[r], mx);
            float alpha = __expf(rm[r] - mnew);
            float sum = 0.f;
#pragma unroll
            for (int c = 0; c < 4; c++) {
                s[r][c] = __expf(s[r][c] - mnew);
                sum += s[r][c];
            }
#pragma unroll
            for (int w = 1; w < 16; w <<= 1)
                sum += __shfl_xor_sync(0xffffffffu, sum, w, 16);
            rl[r] = rl[r] * alpha + sum;
            rm[r] = mnew;
#pragma unroll
            for (int c = 0; c < 4; c++) o[r][c] *= alpha;
#pragma unroll
            for (int c = 0; c < 4; c++)
                Ps[(ty * 4 + r) * 65 + tx * 4 + c] = s[r][c];
        }
        __syncthreads();

#pragma unroll 8
        for (int j = 0; j < 64; j++) {
            float p[4];
#pragma unroll
            for (int r = 0; r < 4; r++) p[r] = Ps[(ty * 4 + r) * 65 + j];
            float4 v = *(const float4*)&Vs[j * 64 + tx * 4];
            float va[4] = {v.x, v.y, v.z, v.w};
#pragma unroll
            for (int r = 0; r < 4; r++)
#pragma unroll
                for (int c = 0; c < 4; c++) o[r][c] += p[r] * va[c];
        }
    }

    const int h = bh & 15;
    const int b = bh >> 4;
#pragma unroll
    for (int r = 0; r < 4; r++) {
        float inv = 1.0f / rl[r];
        int n = qtile * 64 + ty * 4 + r;
        float4 ov;
        ov.x = o[r][0] * inv;
        ov.y = o[r][1] * inv;
        ov.z = o[r][2] * inv;
        ov.w = o[r][3] * inv;
        size_t base = ((size_t)b * SEQ + n) * EMB + h * 64 + tx * 4;
        *(float4*)&g_ctx[base] = ov;
    }
}

// ---------------------------------------------------------------------------
extern "C" void kernel_launch(void* const* d_in, const int* in_sizes, int n_in,
                              void* d_out, int out_size) {
    (void)in_sizes; (void)n_in; (void)out_size;
    const float* x     = (const float*)d_in[0];
    const float* W_qkv = (const float*)d_in[1];
    const float* b_qkv = (const float*)d_in[2];
    const float* W_fc  = (const float*)d_in[3];
    const float* b_fc  = (const float*)d_in[4];
    float* out = (float*)d_out;

    // QKV projection (tensor cores, bf16 split)
    {
        cudaFuncSetAttribute(gemm_mma<0>, cudaFuncAttributeMaxDynamicSharedMemorySize, GSM_TOTAL);
        dim3 grid(3072 / 128, MROWS / 128);
        gemm_mma<0><<<grid, 256, GSM_TOTAL>>>(x, W_qkv, b_qkv, nullptr, 3072);
    }

    // Flash attention (fp32)
    {
        int smem = (3 * 64 * 64 + 64 * 65) * (int)sizeof(float);
        cudaFuncSetAttribute(flash_attn, cudaFuncAttributeMaxDynamicSharedMemorySize, smem);
        dim3 grid(SEQ / 64, BATCH * NHEAD);
        flash_attn<<<grid, 256, smem>>>();
    }

    // Output projection (tensor cores, bf16 split); A resolved in-kernel as g_ctx
    {
        cudaFuncSetAttribute(gemm_mma<1>, cudaFuncAttributeMaxDynamicSharedMemorySize, GSM_TOTAL);
        dim3 grid(1024 / 128, MROWS / 128);
        gemm_mma<1><<<grid, 256, GSM_TOTAL>>>(nullptr, W_fc, b_fc, out, 1024);
    }
}

// round 8
// speedup vs baseline: 2.9097x; 1.8269x over previous
#include <cuda_runtime.h>
#include <cuda_bf16.h>
#include <math.h>
#include <stdint.h>

// Problem constants
#define BATCH   16
#define SEQ     1024
#define EMB     1024
#define NHEAD   16
#define DK      64
#define MROWS   (BATCH * SEQ)        // 16384

// Scratch (device globals; no allocation allowed)
__device__ __nv_bfloat16 g_qh[BATCH * NHEAD * SEQ * DK];
__device__ __nv_bfloat16 g_ql[BATCH * NHEAD * SEQ * DK];
__device__ __nv_bfloat16 g_kh[BATCH * NHEAD * SEQ * DK];
__device__ __nv_bfloat16 g_kl[BATCH * NHEAD * SEQ * DK];
__device__ __nv_bfloat16 g_vh[BATCH * NHEAD * SEQ * DK];
__device__ __nv_bfloat16 g_vl[BATCH * NHEAD * SEQ * DK];
__device__ float g_ctx[BATCH * SEQ * EMB];          // [B,N,D]

// ---------------------------------------------------------------------------
// PTX helpers (legacy tensor-core path; valid on plain sm_103 target)
// ---------------------------------------------------------------------------
__device__ __forceinline__ uint32_t sm_u32(const void* p) {
    uint32_t a;
    asm("{ .reg .u64 t; cvta.to.shared.u64 t, %1; cvt.u32.u64 %0, t; }"
        : "=r"(a) : "l"(p));
    return a;
}
__device__ __forceinline__ void ldsm4(uint32_t addr, uint32_t* r) {
    asm volatile("ldmatrix.sync.aligned.m8n8.x4.shared.b16 {%0,%1,%2,%3}, [%4];"
                 : "=r"(r[0]), "=r"(r[1]), "=r"(r[2]), "=r"(r[3]) : "r"(addr));
}
__device__ __forceinline__ void ldsm4t(uint32_t addr, uint32_t* r) {
    asm volatile("ldmatrix.sync.aligned.m8n8.x4.trans.shared.b16 {%0,%1,%2,%3}, [%4];"
                 : "=r"(r[0]), "=r"(r[1]), "=r"(r[2]), "=r"(r[3]) : "r"(addr));
}
__device__ __forceinline__ void mma16816(float* d, const uint32_t* a, const uint32_t* b) {
    asm volatile(
        "mma.sync.aligned.m16n8k16.row.col.f32.bf16.bf16.f32 "
        "{%0,%1,%2,%3}, {%4,%5,%6,%7}, {%8,%9}, {%0,%1,%2,%3};"
        : "+f"(d[0]), "+f"(d[1]), "+f"(d[2]), "+f"(d[3])
        : "r"(a[0]), "r"(a[1]), "r"(a[2]), "r"(a[3]), "r"(b[0]), "r"(b[1]));
}
__device__ __forceinline__ void cpasync16(uint32_t dst, const void* src) {
    asm volatile("cp.async.cg.shared.global [%0], [%1], 16;" :: "r"(dst), "l"(src));
}
#define CP_COMMIT() asm volatile("cp.async.commit_group;" ::: "memory")
#define CP_WAIT(n)  asm volatile("cp.async.wait_group %0;" :: "n"(n) : "memory")

__device__ __forceinline__ uint32_t pack_bf2(float x, float y) {
    __nv_bfloat162 h = __floats2bfloat162_rn(x, y);
    return *(uint32_t*)&h;
}

// ===========================================================================
// GEMM (unchanged structure from R4; MODE 0 epilogue now emits bf16 hi/lo)
// ===========================================================================
#define A_PITCH 80
#define B_PITCH 272
#define AH_OFF  0
#define AL_OFF  (128 * A_PITCH)
#define BH_OFF  (2 * 128 * A_PITCH)
#define BL_OFF  (BH_OFF + 32 * B_PITCH)
#define BUF_SZ  (BL_OFF + 32 * B_PITCH)
#define GSM_TOTAL (2 * BUF_SZ)

template <int MODE>
__global__ __launch_bounds__(256) void gemm_mma(const float* __restrict__ A_in,
                                                const float* __restrict__ W,
                                                const float* __restrict__ bias,
                                                float* __restrict__ out,
                                                int ldW) {
    extern __shared__ char smem[];
    const uint32_t smb = sm_u32(smem);
    const int tid  = threadIdx.x;
    const int lane = tid & 31;
    const int wid  = tid >> 5;
    const int wm   = wid & 3;
    const int wn   = wid >> 2;
    const int mBase = blockIdx.y * 128;
    const int nBase = blockIdx.x * 128;

    const float* A = (MODE == 1) ? (const float*)g_ctx : A_in;

    float acc[2][8][4];
#pragma unroll
    for (int i = 0; i < 2; i++)
#pragma unroll
        for (int j = 0; j < 8; j++)
#pragma unroll
            for (int q = 0; q < 4; q++) acc[i][j][q] = 0.f;

    float4 ra[4], rb[4];
    const int am = tid >> 3;
    const int aq = tid & 7;
    const int bk = tid >> 5;
    const int bq = tid & 31;

#pragma unroll
    for (int i = 0; i < 4; i++) {
        ra[i] = __ldg((const float4*)(A + (size_t)(mBase + am + i * 32) * 1024 + aq * 4));
        rb[i] = __ldg((const float4*)(W + (size_t)(bk + i * 8) * ldW + nBase + bq * 4));
    }

    auto sts_chunk = [&](int buf) {
        char* base = smem + buf * BUF_SZ;
#pragma unroll
        for (int i = 0; i < 4; i++) {
            float4 v = ra[i];
            __nv_bfloat162 h01 = __floats2bfloat162_rn(v.x, v.y);
            __nv_bfloat162 h23 = __floats2bfloat162_rn(v.z, v.w);
            __nv_bfloat162 l01 = __floats2bfloat162_rn(v.x - __bfloat162float(h01.x),
                                                       v.y - __bfloat162float(h01.y));
            __nv_bfloat162 l23 = __floats2bfloat162_rn(v.z - __bfloat162float(h23.x),
                                                       v.w - __bfloat162float(h23.y));
            int off = (am + i * 32) * A_PITCH + aq * 8;
            *(uint2*)(base + AH_OFF + off) = make_uint2(*(uint32_t*)&h01, *(uint32_t*)&h23);
            *(uint2*)(base + AL_OFF + off) = make_uint2(*(uint32_t*)&l01, *(uint32_t*)&l23);
            float4 w = rb[i];
            __nv_bfloat162 bh01 = __floats2bfloat162_rn(w.x, w.y);
            __nv_bfloat162 bh23 = __floats2bfloat162_rn(w.z, w.w);
            __nv_bfloat162 bl01 = __floats2bfloat162_rn(w.x - __bfloat162float(bh01.x),
                                                        w.y - __bfloat162float(bh01.y));
            __nv_bfloat162 bl23 = __floats2bfloat162_rn(w.z - __bfloat162float(bh23.x),
                                                        w.w - __bfloat162float(bh23.y));
            int boff = (bk + i * 8) * B_PITCH + bq * 8;
            *(uint2*)(base + BH_OFF + boff) = make_uint2(*(uint32_t*)&bh01, *(uint32_t*)&bh23);
            *(uint2*)(base + BL_OFF + boff) = make_uint2(*(uint32_t*)&bl01, *(uint32_t*)&bl23);
        }
    };

    sts_chunk(0);
    __syncthreads();

    for (int c = 0; c < 32; c++) {
        const int buf = c & 1;
        if (c + 1 < 32) {
            const int kOff = (c + 1) * 32;
#pragma unroll
            for (int i = 0; i < 4; i++) {
                ra[i] = __ldg((const float4*)(A + (size_t)(mBase + am + i * 32) * 1024 + kOff + aq * 4));
                rb[i] = __ldg((const float4*)(W + (size_t)(kOff + bk + i * 8) * ldW + nBase + bq * 4));
            }
        }
        const uint32_t sb = smb + buf * BUF_SZ;
#pragma unroll
        for (int ks = 0; ks < 2; ks++) {
            const int k0 = ks * 16;
            uint32_t Ah[2][4], Al[2][4], Bh[8][2], Bl[8][2];
#pragma unroll
            for (int mt = 0; mt < 2; mt++) {
                uint32_t addr = sb + (uint32_t)((wm * 32 + mt * 16 + (lane & 15)) * A_PITCH
                                                + (k0 + (lane >> 4) * 8) * 2);
                ldsm4(addr + AH_OFF, Ah[mt]);
                ldsm4(addr + AL_OFF, Al[mt]);
            }
#pragma unroll
            for (int p = 0; p < 4; p++) {
                uint32_t addr = sb + (uint32_t)((k0 + (lane & 15)) * B_PITCH
                                                + (wn * 64 + p * 16 + (lane >> 4) * 8) * 2);
                uint32_t r[4];
                ldsm4t(addr + BH_OFF, r);
                Bh[2 * p][0] = r[0]; Bh[2 * p][1] = r[1];
                Bh[2 * p + 1][0] = r[2]; Bh[2 * p + 1][1] = r[3];
                ldsm4t(addr + BL_OFF, r);
                Bl[2 * p][0] = r[0]; Bl[2 * p][1] = r[1];
                Bl[2 * p + 1][0] = r[2]; Bl[2 * p + 1][1] = r[3];
            }
#pragma unroll
            for (int mt = 0; mt < 2; mt++)
#pragma unroll
                for (int nt = 0; nt < 8; nt++) mma16816(acc[mt][nt], Ah[mt], Bh[nt]);
#pragma unroll
            for (int mt = 0; mt < 2; mt++)
#pragma unroll
                for (int nt = 0; nt < 8; nt++) mma16816(acc[mt][nt], Ah[mt], Bl[nt]);
#pragma unroll
            for (int mt = 0; mt < 2; mt++)
#pragma unroll
                for (int nt = 0; nt < 8; nt++) mma16816(acc[mt][nt], Al[mt], Bh[nt]);
        }
        __syncthreads();
        if (c + 1 < 32) {
            sts_chunk((c + 1) & 1);
            __syncthreads();
        }
    }

    const int rbase = mBase + wm * 32 + (lane >> 2);
    const int cbase = nBase + wn * 64 + 2 * (lane & 3);
#pragma unroll
    for (int mt = 0; mt < 2; mt++) {
#pragma unroll
        for (int nt = 0; nt < 8; nt++) {
            const int col = cbase + nt * 8;
            const float bx = __ldg(&bias[col]);
            const float by = __ldg(&bias[col + 1]);
#pragma unroll
            for (int half = 0; half < 2; half++) {
                const int row = rbase + mt * 16 + half * 8;
                float vx = acc[mt][nt][half * 2 + 0] + bx;
                float vy = acc[mt][nt][half * 2 + 1] + by;
                if (MODE == 1) {
                    *(float2*)(out + (size_t)row * 1024 + col) = make_float2(vx, vy);
                } else {
                    // emit bf16 hi/lo split directly
                    const int which = col >> 10;
                    const int h = (col >> 6) & 15;
                    const int d0 = col & 63;
                    const int b = row >> 10;
                    const int n_tok = row & 1023;
                    size_t idx = ((size_t)(b * NHEAD + h) * SEQ + n_tok) * DK + d0;
                    __nv_bfloat16 hx = __float2bfloat16_rn(vx);
                    __nv_bfloat16 hy = __float2bfloat16_rn(vy);
                    __nv_bfloat162 hv = {hx, hy};
                    __nv_bfloat162 lv = {__float2bfloat16_rn(vx - __bfloat162float(hx)),
                                         __float2bfloat16_rn(vy - __bfloat162float(hy))};
                    __nv_bfloat16* dh = (which == 0) ? g_qh : (which == 1) ? g_kh : g_vh;
                    __nv_bfloat16* dl = (which == 0) ? g_ql : (which == 1) ? g_kl : g_vl;
                    *(__nv_bfloat162*)(dh + idx) = hv;
                    *(__nv_bfloat162*)(dl + idx) = lv;
                }
            }
        }
    }
}

// ===========================================================================
// Flash attention on tensor cores.  CTA = 128 q rows x one (b,h).
// 8 warps x 16 q rows.  K-chunks of 64, cp.async double buffered.
// ===========================================================================
#define FA_PITCH  144                          // 64 bf16 = 128B + 16 pad
#define FA_QH     0
#define FA_QL     (128 * FA_PITCH)             // 18432
#define FA_KV0    (2 * 128 * FA_PITCH)         // 36864
#define FA_KVSZ   (4 * 64 * FA_PITCH)          // 36864 per buffer (KH,KL,VH,VL)
#define FA_KH     0
#define FA_KL     (64 * FA_PITCH)
#define FA_VH     (2 * 64 * FA_PITCH)
#define FA_VL     (3 * 64 * FA_PITCH)
#define FA_TOTAL  (FA_KV0 + 2 * FA_KVSZ)       // 110592

__global__ __launch_bounds__(256, 1) void flash_attn_tc() {
    extern __shared__ char smem[];
    const uint32_t smb = sm_u32(smem);
    const int tid  = threadIdx.x;
    const int lane = tid & 31;
    const int wid  = tid >> 5;
    const int qtile = blockIdx.x;           // 0..7 (128 q rows each)
    const int bh    = blockIdx.y;           // 0..255

    const size_t headOff = (size_t)bh * SEQ * DK;
    const __nv_bfloat16* Qh = g_qh + headOff + (size_t)qtile * 128 * DK;
    const __nv_bfloat16* Ql = g_ql + headOff + (size_t)qtile * 128 * DK;

    // ---- prologue: cp.async Q tile (hi+lo) + KV chunk 0; one group ----
    {
        // Q: 128 rows x 8 x16B per tile; 1024 ops/tile; 4 per thread per tile
#pragma unroll
        for (int i = 0; i < 4; i++) {
            int idx = tid + i * 256;        // 0..1023
            int r = idx >> 3, c16 = idx & 7;
            cpasync16(smb + FA_QH + r * FA_PITCH + c16 * 16, (const char*)Qh + r * 128 + c16 * 16);
            cpasync16(smb + FA_QL + r * FA_PITCH + c16 * 16, (const char*)Ql + r * 128 + c16 * 16);
        }
        // KV chunk 0: 4 tiles x 64 rows x 8 x16B = 2048 ops; 8 per thread
        const __nv_bfloat16* src[4] = {g_kh + headOff, g_kl + headOff,
                                       g_vh + headOff, g_vl + headOff};
#pragma unroll
        for (int t4 = 0; t4 < 4; t4++) {
#pragma unroll
            for (int i = 0; i < 2; i++) {
                int idx = tid + i * 256;    // 0..511
                int r = idx >> 3, c16 = idx & 7;
                cpasync16(smb + FA_KV0 + t4 * (64 * FA_PITCH) + r * FA_PITCH + c16 * 16,
                          (const char*)src[t4] + r * 128 + c16 * 16);
            }
        }
        CP_COMMIT();
    }

    // persistent state
    uint32_t QHf[4][4], QLf[4][4];          // A frags, 4 dk-steps
    float S[8][4];                          // scores 16q x 64n
    float O[8][4];                          // out acc 16q x 64dk
    float m0 = -INFINITY, m1 = -INFINITY, l0 = 0.f, l1 = 0.f;
#pragma unroll
    for (int nt = 0; nt < 8; nt++)
#pragma unroll
        for (int j = 0; j < 4; j++) O[nt][j] = 0.f;

    const __nv_bfloat16* Kh = g_kh + headOff;
    const __nv_bfloat16* Kl = g_kl + headOff;
    const __nv_bfloat16* Vh = g_vh + headOff;
    const __nv_bfloat16* Vl = g_vl + headOff;

    for (int c = 0; c < 16; c++) {
        const uint32_t kv = smb + FA_KV0 + (c & 1) * FA_KVSZ;

        if (c > 0) __syncthreads();         // protect buf^1 WAR

        if (c + 1 < 16) {                   // prefetch next chunk
            const uint32_t nkv = smb + FA_KV0 + ((c + 1) & 1) * FA_KVSZ;
            const int rowOff = (c + 1) * 64;
            const __nv_bfloat16* src[4] = {Kh, Kl, Vh, Vl};
#pragma unroll
            for (int t4 = 0; t4 < 4; t4++) {
#pragma unroll
                for (int i = 0; i < 2; i++) {
                    int idx = tid + i * 256;
                    int r = idx >> 3, c16 = idx & 7;
                    cpasync16(nkv + t4 * (64 * FA_PITCH) + r * FA_PITCH + c16 * 16,
                              (const char*)src[t4] + (size_t)(rowOff + r) * 128 + c16 * 16);
                }
            }
            CP_COMMIT();
            CP_WAIT(1);
        } else {
            CP_WAIT(0);
        }
        __syncthreads();

        if (c == 0) {                       // load persistent Q frags
#pragma unroll
            for (int ks = 0; ks < 4; ks++) {
                uint32_t addr = smb + (uint32_t)((wid * 16 + (lane & 15)) * FA_PITCH
                                                 + (ks * 16 + (lane >> 4) * 8) * 2);
                ldsm4(addr + FA_QH, QHf[ks]);
                ldsm4(addr + FA_QL, QLf[ks]);
            }
        }

        // ---- S = Q K^T (split, 3 terms) ----
#pragma unroll
        for (int nt = 0; nt < 8; nt++)
#pragma unroll
            for (int j = 0; j < 4; j++) S[nt][j] = 0.f;

#pragma unroll
        for (int p = 0; p < 4; p++) {       // 16 seq-n each
            uint32_t bh_[4][2][2], bl_[4][2][2];
#pragma unroll
            for (int ks = 0; ks < 4; ks++) {
                uint32_t addr = kv + (uint32_t)((p * 16 + (lane & 15)) * FA_PITCH
                                                + (ks * 16 + (lane >> 4) * 8) * 2);
                uint32_t r[4];
                ldsm4(addr + FA_KH, r);     // non-trans: [n][k] rows -> B frags
                bh_[ks][0][0] = r[0]; bh_[ks][0][1] = r[2];
                bh_[ks][1][0] = r[1]; bh_[ks][1][1] = r[3];
                ldsm4(addr + FA_KL, r);
                bl_[ks][0][0] = r[0]; bl_[ks][0][1] = r[2];
                bl_[ks][1][0] = r[1]; bl_[ks][1][1] = r[3];
            }
#pragma unroll
            for (int ks = 0; ks < 4; ks++) {
#pragma unroll
                for (int nt = 0; nt < 2; nt++) {
                    mma16816(S[2 * p + nt], QHf[ks], bh_[ks][nt]);
                    mma16816(S[2 * p + nt], QHf[ks], bl_[ks][nt]);
                    mma16816(S[2 * p + nt], QLf[ks], bh_[ks][nt]);
                }
            }
        }

        // ---- online softmax ----
        float mx0 = -INFINITY, mx1 = -INFINITY;
#pragma unroll
        for (int nt = 0; nt < 8; nt++) {
            S[nt][0] *= 0.125f; S[nt][1] *= 0.125f;
            S[nt][2] *= 0.125f; S[nt][3] *= 0.125f;
            mx0 = fmaxf(mx0, fmaxf(S[nt][0], S[nt][1]));
            mx1 = fmaxf(mx1, fmaxf(S[nt][2], S[nt][3]));
        }
        mx0 = fmaxf(mx0, __shfl_xor_sync(0xffffffffu, mx0, 1));
        mx0 = fmaxf(mx0, __shfl_xor_sync(0xffffffffu, mx0, 2));
        mx1 = fmaxf(mx1, __shfl_xor_sync(0xffffffffu, mx1, 1));
        mx1 = fmaxf(mx1, __shfl_xor_sync(0xffffffffu, mx1, 2));
        const float nm0 = fmaxf(m0, mx0), nm1 = fmaxf(m1, mx1);
        const float a0 = __expf(m0 - nm0), a1 = __expf(m1 - nm1);
        m0 = nm0; m1 = nm1;
        float s0 = 0.f, s1 = 0.f;
#pragma unroll
        for (int nt = 0; nt < 8; nt++) {
            S[nt][0] = __expf(S[nt][0] - nm0);
            S[nt][1] = __expf(S[nt][1] - nm0);
            S[nt][2] = __expf(S[nt][2] - nm1);
            S[nt][3] = __expf(S[nt][3] - nm1);
            s0 += S[nt][0] + S[nt][1];
            s1 += S[nt][2] + S[nt][3];
        }
        s0 += __shfl_xor_sync(0xffffffffu, s0, 1);
        s0 += __shfl_xor_sync(0xffffffffu, s0, 2);
        s1 += __shfl_xor_sync(0xffffffffu, s1, 1);
        s1 += __shfl_xor_sync(0xffffffffu, s1, 2);
        l0 = l0 * a0 + s0;
        l1 = l1 * a1 + s1;
#pragma unroll
        for (int nt = 0; nt < 8; nt++) {
            O[nt][0] *= a0; O[nt][1] *= a0;
            O[nt][2] *= a1; O[nt][3] *= a1;
        }

        // ---- O += P V (split, 3 terms); P a-frags built from S regs ----
#pragma unroll
        for (int kt = 0; kt < 4; kt++) {
            uint32_t ah[4], al[4];
            {
                float e0 = S[2 * kt][0], e1 = S[2 * kt][1];
                float e2 = S[2 * kt][2], e3 = S[2 * kt][3];
                float f0 = S[2 * kt + 1][0], f1 = S[2 * kt + 1][1];
                float f2 = S[2 * kt + 1][2], f3 = S[2 * kt + 1][3];
                ah[0] = pack_bf2(e0, e1); ah[1] = pack_bf2(e2, e3);
                ah[2] = pack_bf2(f0, f1); ah[3] = pack_bf2(f2, f3);
                __nv_bfloat162* hp;
                hp = (__nv_bfloat162*)&ah[0];
                al[0] = pack_bf2(e0 - __bfloat162float(hp->x), e1 - __bfloat162float(hp->y));
                hp = (__nv_bfloat162*)&ah[1];
                al[1] = pack_bf2(e2 - __bfloat162float(hp->x), e3 - __bfloat162float(hp->y));
                hp = (__nv_bfloat162*)&ah[2];
                al[2] = pack_bf2(f0 - __bfloat162float(hp->x), f1 - __bfloat162float(hp->y));
                hp = (__nv_bfloat162*)&ah[3];
                al[3] = pack_bf2(f2 - __bfloat162float(hp->x), f3 - __bfloat162float(hp->y));
            }
#pragma unroll
            for (int p = 0; p < 4; p++) {   // dk, 16 each
                uint32_t addr = kv + (uint32_t)((kt * 16 + (lane & 15)) * FA_PITCH
                                                + (p * 16 + (lane >> 4) * 8) * 2);
                uint32_t r[4], vh_[2][2], vl_[2][2];
                ldsm4t(addr + FA_VH, r);    // trans: [k][n] rows -> B frags
                vh_[0][0] = r[0]; vh_[0][1] = r[1];
                vh_[1][0] = r[2]; vh_[1][1] = r[3];
                ldsm4t(addr + FA_VL, r);
                vl_[0][0] = r[0]; vl_[0][1] = r[1];
                vl_[1][0] = r[2]; vl_[1][1] = r[3];
#pragma unroll
                for (int nt = 0; nt < 2; nt++) {
                    mma16816(O[2 * p + nt], ah, vh_[nt]);
                    mma16816(O[2 * p + nt], ah, vl_[nt]);
                    mma16816(O[2 * p + nt], al, vh_[nt]);
                }
            }
        }
    }

    // ---- normalize + write ctx [B,N,D] ----
    const int h = bh & 15;
    const int b = bh >> 4;
    const float i0 = 1.f / l0, i1 = 1.f / l1;
    const int r0 = qtile * 128 + wid * 16 + (lane >> 2);
    const int colb = h * 64 + 2 * (lane & 3);
#pragma unroll
    for (int nt = 0; nt < 8; nt++) {
        const int col = colb + nt * 8;
        *(float2*)&g_ctx[((size_t)b * SEQ + r0) * EMB + col] =
            make_float2(O[nt][0] * i0, O[nt][1] * i0);
        *(float2*)&g_ctx[((size_t)b * SEQ + r0 + 8) * EMB + col] =
            make_float2(O[nt][2] * i1, O[nt][3] * i1);
    }
}

// ---------------------------------------------------------------------------
extern "C" void kernel_launch(void* const* d_in, const int* in_sizes, int n_in,
                              void* d_out, int out_size) {
    (void)in_sizes; (void)n_in; (void)out_size;
    const float* x     = (const float*)d_in[0];
    const float* W_qkv = (const float*)d_in[1];
    const float* b_qkv = (const float*)d_in[2];
    const float* W_fc  = (const float*)d_in[3];
    const float* b_fc  = (const float*)d_in[4];
    float* out = (float*)d_out;

    // QKV projection (tensor cores, bf16 split; epilogue emits hi/lo bf16)
    {
        cudaFuncSetAttribute(gemm_mma<0>, cudaFuncAttributeMaxDynamicSharedMemorySize, GSM_TOTAL);
        dim3 grid(3072 / 128, MROWS / 128);
        gemm_mma<0><<<grid, 256, GSM_TOTAL>>>(x, W_qkv, b_qkv, nullptr, 3072);
    }

    // Flash attention (tensor cores, split QK^T and PV)
    {
        cudaFuncSetAttribute(flash_attn_tc, cudaFuncAttributeMaxDynamicSharedMemorySize, FA_TOTAL);
        dim3 grid(SEQ / 128, BATCH * NHEAD);
        flash_attn_tc<<<grid, 256, FA_TOTAL>>>();
    }

    // Output projection (tensor cores, bf16 split); A resolved in-kernel as g_ctx
    {
        cudaFuncSetAttribute(gemm_mma<1>, cudaFuncAttributeMaxDynamicSharedMemorySize, GSM_TOTAL);
        dim3 grid(1024 / 128, MROWS / 128);
        gemm_mma<1><<<grid, 256, GSM_TOTAL>>>(nullptr, W_fc, b_fc, out, 1024);
    }
}

// round 9
// speedup vs baseline: 2.9629x; 1.0183x over previous
#include <cuda_runtime.h>
#include <cuda_bf16.h>
#include <math.h>
#include <stdint.h>

// Problem constants
#define BATCH   16
#define SEQ     1024
#define EMB     1024
#define NHEAD   16
#define DK      64
#define MROWS   (BATCH * SEQ)        // 16384

// Scratch (device globals; no allocation allowed)
__device__ __nv_bfloat16 g_xh[MROWS * EMB], g_xl[MROWS * EMB];          // x split
__device__ __nv_bfloat16 g_wqh[EMB * 3072], g_wql[EMB * 3072];          // W_qkv split
__device__ __nv_bfloat16 g_wfh[EMB * EMB],  g_wfl[EMB * EMB];           // W_fc split
__device__ __nv_bfloat16 g_qh[BATCH * NHEAD * SEQ * DK], g_ql[BATCH * NHEAD * SEQ * DK];
__device__ __nv_bfloat16 g_kh[BATCH * NHEAD * SEQ * DK], g_kl[BATCH * NHEAD * SEQ * DK];
__device__ __nv_bfloat16 g_vh[BATCH * NHEAD * SEQ * DK], g_vl[BATCH * NHEAD * SEQ * DK];
__device__ __nv_bfloat16 g_ch[MROWS * EMB], g_cl[MROWS * EMB];          // ctx split

// ---------------------------------------------------------------------------
// PTX helpers
// ---------------------------------------------------------------------------
__device__ __forceinline__ uint32_t sm_u32(const void* p) {
    uint32_t a;
    asm("{ .reg .u64 t; cvta.to.shared.u64 t, %1; cvt.u32.u64 %0, t; }"
        : "=r"(a) : "l"(p));
    return a;
}
__device__ __forceinline__ void ldsm4(uint32_t addr, uint32_t* r) {
    asm volatile("ldmatrix.sync.aligned.m8n8.x4.shared.b16 {%0,%1,%2,%3}, [%4];"
                 : "=r"(r[0]), "=r"(r[1]), "=r"(r[2]), "=r"(r[3]) : "r"(addr));
}
__device__ __forceinline__ void ldsm4t(uint32_t addr, uint32_t* r) {
    asm volatile("ldmatrix.sync.aligned.m8n8.x4.trans.shared.b16 {%0,%1,%2,%3}, [%4];"
                 : "=r"(r[0]), "=r"(r[1]), "=r"(r[2]), "=r"(r[3]) : "r"(addr));
}
__device__ __forceinline__ void mma16816(float* d, const uint32_t* a, const uint32_t* b) {
    asm volatile(
        "mma.sync.aligned.m16n8k16.row.col.f32.bf16.bf16.f32 "
        "{%0,%1,%2,%3}, {%4,%5,%6,%7}, {%8,%9}, {%0,%1,%2,%3};"
        : "+f"(d[0]), "+f"(d[1]), "+f"(d[2]), "+f"(d[3])
        : "r"(a[0]), "r"(a[1]), "r"(a[2]), "r"(a[3]), "r"(b[0]), "r"(b[1]));
}
__device__ __forceinline__ void cpasync16(uint32_t dst, const void* src) {
    asm volatile("cp.async.cg.shared.global [%0], [%1], 16;" :: "r"(dst), "l"(src));
}
#define CP_COMMIT() asm volatile("cp.async.commit_group;" ::: "memory")
#define CP_WAIT(n)  asm volatile("cp.async.wait_group %0;" :: "n"(n) : "memory")

__device__ __forceinline__ uint32_t pack_bf2(float x, float y) {
    __nv_bfloat162 h = __floats2bfloat162_rn(x, y);
    return *(uint32_t*)&h;
}

// ---------------------------------------------------------------------------
// Pre-split: fp32 -> bf16 hi/lo planes.  which: 0=x 1=W_qkv 2=W_fc
// ---------------------------------------------------------------------------
__global__ __launch_bounds__(256) void split_f32(const float* __restrict__ src,
                                                 int which, int n4) {
    int i = blockIdx.x * 256 + threadIdx.x;
    if (i >= n4) return;
    __nv_bfloat16* hi = (which == 0) ? g_xh : (which == 1) ? g_wqh : g_wfh;
    __nv_bfloat16* lo = (which == 0) ? g_xl : (which == 1) ? g_wql : g_wfl;
    float4 v = __ldg((const float4*)src + i);
    __nv_bfloat162 h01 = __floats2bfloat162_rn(v.x, v.y);
    __nv_bfloat162 h23 = __floats2bfloat162_rn(v.z, v.w);
    __nv_bfloat162 l01 = __floats2bfloat162_rn(v.x - __bfloat162float(h01.x),
                                               v.y - __bfloat162float(h01.y));
    __nv_bfloat162 l23 = __floats2bfloat162_rn(v.z - __bfloat162float(h23.x),
                                               v.w - __bfloat162float(h23.y));
    *(uint2*)(hi + 4 * (size_t)i) = make_uint2(*(uint32_t*)&h01, *(uint32_t*)&h23);
    *(uint2*)(lo + 4 * (size_t)i) = make_uint2(*(uint32_t*)&l01, *(uint32_t*)&l23);
}

// ===========================================================================
// bf16-presplit GEMM: out[16384,N] = A @ W + bias.  cp.async 3-stage.
// MODE 0: A=x-split, W=Wqkv-split (N=3072), scatter q/k/v hi/lo.
// MODE 1: A=ctx-split, W=Wfc-split (N=1024), fp32 out.
// ===========================================================================
#define SA_PITCH 80                 // 32 bf16 = 64B + 16 pad
#define SB_PITCH 272                // 128 bf16 = 256B + 16 pad
#define ST_AH 0
#define ST_AL (128 * SA_PITCH)      // 10240
#define ST_BH (2 * 128 * SA_PITCH)  // 20480
#define ST_BL (ST_BH + 32 * SB_PITCH)
#define ST_SZ (ST_BL + 32 * SB_PITCH)   // 37888
#define G2_TOTAL (3 * ST_SZ)            // 113664

template <int MODE>
__global__ __launch_bounds__(256) void gemm_bf(const float* __restrict__ bias,
                                               float* __restrict__ out) {
    extern __shared__ char smem[];
    const uint32_t smb = sm_u32(smem);
    const int tid  = threadIdx.x;
    const int lane = tid & 31;
    const int wid  = tid >> 5;
    const int wm   = wid & 3;
    const int wn   = wid >> 2;
    const int mBase = blockIdx.y * 128;
    const int nBase = blockIdx.x * 128;
    const int ldW = (MODE == 0) ? 3072 : 1024;

    const __nv_bfloat16* Ah = (MODE == 0) ? g_xh : g_ch;
    const __nv_bfloat16* Al = (MODE == 0) ? g_xl : g_cl;
    const __nv_bfloat16* Bh = (MODE == 0) ? g_wqh : g_wfh;
    const __nv_bfloat16* Bl = (MODE == 0) ? g_wql : g_wfl;

    float acc[2][8][4];
#pragma unroll
    for (int i = 0; i < 2; i++)
#pragma unroll
        for (int j = 0; j < 8; j++)
#pragma unroll
            for (int q = 0; q < 4; q++) acc[i][j][q] = 0.f;

    auto load_stage = [&](int stage, int kc) {
        const uint32_t sb = smb + stage * ST_SZ;
        const int kOff = kc * 32;
#pragma unroll
        for (int i = 0; i < 2; i++) {
            int idx = tid + i * 256;                 // 0..511
            int r = idx >> 2, ch = idx & 3;          // A: 128 rows x 4 chunks
            const size_t go = (size_t)(mBase + r) * 1024 + kOff + ch * 8;
            cpasync16(sb + ST_AH + r * SA_PITCH + ch * 16, Ah + go);
            cpasync16(sb + ST_AL + r * SA_PITCH + ch * 16, Al + go);
        }
#pragma unroll
        for (int i = 0; i < 2; i++) {
            int idx = tid + i * 256;                 // 0..511
            int r = idx >> 4, ch = idx & 15;         // B: 32 rows x 16 chunks
            const size_t go = (size_t)(kOff + r) * ldW + nBase + ch * 8;
            cpasync16(sb + ST_BH + r * SB_PITCH + ch * 16, Bh + go);
            cpasync16(sb + ST_BL + r * SB_PITCH + ch * 16, Bl + go);
        }
        CP_COMMIT();
    };

    load_stage(0, 0);
    load_stage(1, 1);

    for (int c = 0; c < 32; c++) {
        const int st = c % 3;
        if (c < 31) { CP_WAIT(1); } else { CP_WAIT(0); }
        __syncthreads();                             // prev reads of stage (c+2)%3 done
        if (c + 2 < 32) load_stage((c + 2) % 3, c + 2);

        const uint32_t sb = smb + st * ST_SZ;
#pragma unroll
        for (int ks = 0; ks < 2; ks++) {
            const int k0 = ks * 16;
            uint32_t Ahf[2][4], Alf[2][4];
#pragma unroll
            for (int mt = 0; mt < 2; mt++) {
                uint32_t addr = sb + (uint32_t)((wm * 32 + mt * 16 + (lane & 15)) * SA_PITCH
                                                + (k0 + (lane >> 4) * 8) * 2);
                ldsm4(addr + ST_AH, Ahf[mt]);
                ldsm4(addr + ST_AL, Alf[mt]);
            }
#pragma unroll
            for (int p = 0; p < 4; p++) {
                uint32_t addr = sb + (uint32_t)((k0 + (lane & 15)) * SB_PITCH
                                                + (wn * 64 + p * 16 + (lane >> 4) * 8) * 2);
                uint32_t r[4], bh_[2][2], bl_[2][2];
                ldsm4t(addr + ST_BH, r);
                bh_[0][0] = r[0]; bh_[0][1] = r[1];
                bh_[1][0] = r[2]; bh_[1][1] = r[3];
                ldsm4t(addr + ST_BL, r);
                bl_[0][0] = r[0]; bl_[0][1] = r[1];
                bl_[1][0] = r[2]; bl_[1][1] = r[3];
#pragma unroll
                for (int mt = 0; mt < 2; mt++)
#pragma unroll
                    for (int nt = 0; nt < 2; nt++) {
                        float* d = acc[mt][2 * p + nt];
                        mma16816(d, Ahf[mt], bh_[nt]);
                        mma16816(d, Ahf[mt], bl_[nt]);
                        mma16816(d, Alf[mt], bh_[nt]);
                    }
            }
        }
        __syncthreads();                             // stage st reads done before refill
    }

    // ---- epilogue ----
    const int rbase = mBase + wm * 32 + (lane >> 2);
    const int cbase = nBase + wn * 64 + 2 * (lane & 3);
#pragma unroll
    for (int mt = 0; mt < 2; mt++) {
#pragma unroll
        for (int nt = 0; nt < 8; nt++) {
            const int col = cbase + nt * 8;
            const float bx = __ldg(&bias[col]);
            const float by = __ldg(&bias[col + 1]);
#pragma unroll
            for (int half = 0; half < 2; half++) {
                const int row = rbase + mt * 16 + half * 8;
                float vx = acc[mt][nt][half * 2 + 0] + bx;
                float vy = acc[mt][nt][half * 2 + 1] + by;
                if (MODE == 1) {
                    *(float2*)(out + (size_t)row * 1024 + col) = make_float2(vx, vy);
                } else {
                    const int which = col >> 10;
                    const int h = (col >> 6) & 15;
                    const int d0 = col & 63;
                    const int b = row >> 10;
                    const int n_tok = row & 1023;
                    size_t idx = ((size_t)(b * NHEAD + h) * SEQ + n_tok) * DK + d0;
                    __nv_bfloat16 hx = __float2bfloat16_rn(vx);
                    __nv_bfloat16 hy = __float2bfloat16_rn(vy);
                    __nv_bfloat162 hv = {hx, hy};
                    __nv_bfloat162 lv = {__float2bfloat16_rn(vx - __bfloat162float(hx)),
                                         __float2bfloat16_rn(vy - __bfloat162float(hy))};
                    __nv_bfloat16* dh = (which == 0) ? g_qh : (which == 1) ? g_kh : g_vh;
                    __nv_bfloat16* dl = (which == 0) ? g_ql : (which == 1) ? g_kl : g_vl;
                    *(__nv_bfloat162*)(dh + idx) = hv;
                    *(__nv_bfloat162*)(dl + idx) = lv;
                }
            }
        }
    }
}

// ===========================================================================
// Flash attention on tensor cores.  CTA = 128 q rows x one (b,h).
// ===========================================================================
#define FA_PITCH  144
#define FA_QH     0
#define FA_QL     (128 * FA_PITCH)
#define FA_KV0    (2 * 128 * FA_PITCH)
#define FA_KVSZ   (4 * 64 * FA_PITCH)
#define FA_KH     0
#define FA_KL     (64 * FA_PITCH)
#define FA_VH     (2 * 64 * FA_PITCH)
#define FA_VL     (3 * 64 * FA_PITCH)
#define FA_TOTAL  (FA_KV0 + 2 * FA_KVSZ)       // 110592

__global__ __launch_bounds__(256, 1) void flash_attn_tc() {
    extern __shared__ char smem[];
    const uint32_t smb = sm_u32(smem);
    const int tid  = threadIdx.x;
    const int lane = tid & 31;
    const int wid  = tid >> 5;
    const int qtile = blockIdx.x;
    const int bh    = blockIdx.y;

    const size_t headOff = (size_t)bh * SEQ * DK;
    const __nv_bfloat16* Qh = g_qh + headOff + (size_t)qtile * 128 * DK;
    const __nv_bfloat16* Ql = g_ql + headOff + (size_t)qtile * 128 * DK;

    {
#pragma unroll
        for (int i = 0; i < 4; i++) {
            int idx = tid + i * 256;
            int r = idx >> 3, c16 = idx & 7;
            cpasync16(smb + FA_QH + r * FA_PITCH + c16 * 16, (const char*)Qh + r * 128 + c16 * 16);
            cpasync16(smb + FA_QL + r * FA_PITCH + c16 * 16, (const char*)Ql + r * 128 + c16 * 16);
        }
        const __nv_bfloat16* src[4] = {g_kh + headOff, g_kl + headOff,
                                       g_vh + headOff, g_vl + headOff};
#pragma unroll
        for (int t4 = 0; t4 < 4; t4++) {
#pragma unroll
            for (int i = 0; i < 2; i++) {
                int idx = tid + i * 256;
                int r = idx >> 3, c16 = idx & 7;
                cpasync16(smb + FA_KV0 + t4 * (64 * FA_PITCH) + r * FA_PITCH + c16 * 16,
                          (const char*)src[t4] + r * 128 + c16 * 16);
            }
        }
        CP_COMMIT();
    }

    uint32_t QHf[4][4], QLf[4][4];
    float S[8][4];
    float O[8][4];
    float m0 = -INFINITY, m1 = -INFINITY, l0 = 0.f, l1 = 0.f;
#pragma unroll
    for (int nt = 0; nt < 8; nt++)
#pragma unroll
        for (int j = 0; j < 4; j++) O[nt][j] = 0.f;

    const __nv_bfloat16* Kh = g_kh + headOff;
    const __nv_bfloat16* Kl = g_kl + headOff;
    const __nv_bfloat16* Vh = g_vh + headOff;
    const __nv_bfloat16* Vl = g_vl + headOff;

    for (int c = 0; c < 16; c++) {
        const uint32_t kv = smb + FA_KV0 + (c & 1) * FA_KVSZ;

        if (c > 0) __syncthreads();

        if (c + 1 < 16) {
            const uint32_t nkv = smb + FA_KV0 + ((c + 1) & 1) * FA_KVSZ;
            const int rowOff = (c + 1) * 64;
            const __nv_bfloat16* src[4] = {Kh, Kl, Vh, Vl};
#pragma unroll
            for (int t4 = 0; t4 < 4; t4++) {
#pragma unroll
                for (int i = 0; i < 2; i++) {
                    int idx = tid + i * 256;
                    int r = idx >> 3, c16 = idx & 7;
                    cpasync16(nkv + t4 * (64 * FA_PITCH) + r * FA_PITCH + c16 * 16,
                              (const char*)src[t4] + (size_t)(rowOff + r) * 128 + c16 * 16);
                }
            }
            CP_COMMIT();
            CP_WAIT(1);
        } else {
            CP_WAIT(0);
        }
        __syncthreads();

        if (c == 0) {
#pragma unroll
            for (int ks = 0; ks < 4; ks++) {
                uint32_t addr = smb + (uint32_t)((wid * 16 + (lane & 15)) * FA_PITCH
                                                 + (ks * 16 + (lane >> 4) * 8) * 2);
                ldsm4(addr + FA_QH, QHf[ks]);
                ldsm4(addr + FA_QL, QLf[ks]);
            }
        }

#pragma unroll
        for (int nt = 0; nt < 8; nt++)
#pragma unroll
            for (int j = 0; j < 4; j++) S[nt][j] = 0.f;

#pragma unroll
        for (int p = 0; p < 4; p++) {
            uint32_t bh_[4][2][2], bl_[4][2][2];
#pragma unroll
            for (int ks = 0; ks < 4; ks++) {
                uint32_t addr = kv + (uint32_t)((p * 16 + (lane & 15)) * FA_PITCH
                                                + (ks * 16 + (lane >> 4) * 8) * 2);
                uint32_t r[4];
                ldsm4(addr + FA_KH, r);
                bh_[ks][0][0] = r[0]; bh_[ks][0][1] = r[2];
                bh_[ks][1][0] = r[1]; bh_[ks][1][1] = r[3];
                ldsm4(addr + FA_KL, r);
                bl_[ks][0][0] = r[0]; bl_[ks][0][1] = r[2];
                bl_[ks][1][0] = r[1]; bl_[ks][1][1] = r[3];
            }
#pragma unroll
            for (int ks = 0; ks < 4; ks++) {
#pragma unroll
                for (int nt = 0; nt < 2; nt++) {
                    mma16816(S[2 * p + nt], QHf[ks], bh_[ks][nt]);
                    mma16816(S[2 * p + nt], QHf[ks], bl_[ks][nt]);
                    mma16816(S[2 * p + nt], QLf[ks], bh_[ks][nt]);
                }
            }
        }

        float mx0 = -INFINITY, mx1 = -INFINITY;
#pragma unroll
        for (int nt = 0; nt < 8; nt++) {
            S[nt][0] *= 0.125f; S[nt][1] *= 0.125f;
            S[nt][2] *= 0.125f; S[nt][3] *= 0.125f;
            mx0 = fmaxf(mx0, fmaxf(S[nt][0], S[nt][1]));
            mx1 = fmaxf(mx1, fmaxf(S[nt][2], S[nt][3]));
        }
        mx0 = fmaxf(mx0, __shfl_xor_sync(0xffffffffu, mx0, 1));
        mx0 = fmaxf(mx0, __shfl_xor_sync(0xffffffffu, mx0, 2));
        mx1 = fmaxf(mx1, __shfl_xor_sync(0xffffffffu, mx1, 1));
        mx1 = fmaxf(mx1, __shfl_xor_sync(0xffffffffu, mx1, 2));
        const float nm0 = fmaxf(m0, mx0), nm1 = fmaxf(m1, mx1);
        const float a0 = __expf(m0 - nm0), a1 = __expf(m1 - nm1);
        m0 = nm0; m1 = nm1;
        float s0 = 0.f, s1 = 0.f;
#pragma unroll
        for (int nt = 0; nt < 8; nt++) {
            S[nt][0] = __expf(S[nt][0] - nm0);
            S[nt][1] = __expf(S[nt][1] - nm0);
            S[nt][2] = __expf(S[nt][2] - nm1);
            S[nt][3] = __expf(S[nt][3] - nm1);
            s0 += S[nt][0] + S[nt][1];
            s1 += S[nt][2] + S[nt][3];
        }
        s0 += __shfl_xor_sync(0xffffffffu, s0, 1);
        s0 += __shfl_xor_sync(0xffffffffu, s0, 2);
        s1 += __shfl_xor_sync(0xffffffffu, s1, 1);
        s1 += __shfl_xor_sync(0xffffffffu, s1, 2);
        l0 = l0 * a0 + s0;
        l1 = l1 * a1 + s1;
#pragma unroll
        for (int nt = 0; nt < 8; nt++) {
            O[nt][0] *= a0; O[nt][1] *= a0;
            O[nt][2] *= a1; O[nt][3] *= a1;
        }

#pragma unroll
        for (int kt = 0; kt < 4; kt++) {
            uint32_t ah[4], al[4];
            {
                float e0 = S[2 * kt][0], e1 = S[2 * kt][1];
                float e2 = S[2 * kt][2], e3 = S[2 * kt][3];
                float f0 = S[2 * kt + 1][0], f1 = S[2 * kt + 1][1];
                float f2 = S[2 * kt + 1][2], f3 = S[2 * kt + 1][3];
                ah[0] = pack_bf2(e0, e1); ah[1] = pack_bf2(e2, e3);
                ah[2] = pack_bf2(f0, f1); ah[3] = pack_bf2(f2, f3);
                __nv_bfloat162* hp;
                hp = (__nv_bfloat162*)&ah[0];
                al[0] = pack_bf2(e0 - __bfloat162float(hp->x), e1 - __bfloat162float(hp->y));
                hp = (__nv_bfloat162*)&ah[1];
                al[1] = pack_bf2(e2 - __bfloat162float(hp->x), e3 - __bfloat162float(hp->y));
                hp = (__nv_bfloat162*)&ah[2];
                al[2] = pack_bf2(f0 - __bfloat162float(hp->x), f1 - __bfloat162float(hp->y));
                hp = (__nv_bfloat162*)&ah[3];
                al[3] = pack_bf2(f2 - __bfloat162float(hp->x), f3 - __bfloat162float(hp->y));
            }
#pragma unroll
            for (int p = 0; p < 4; p++) {
                uint32_t addr = kv + (uint32_t)((kt * 16 + (lane & 15)) * FA_PITCH
                                                + (p * 16 + (lane >> 4) * 8) * 2);
                uint32_t r[4], vh_[2][2], vl_[2][2];
                ldsm4t(addr + FA_VH, r);
                vh_[0][0] = r[0]; vh_[0][1] = r[1];
                vh_[1][0] = r[2]; vh_[1][1] = r[3];
                ldsm4t(addr + FA_VL, r);
                vl_[0][0] = r[0]; vl_[0][1] = r[1];
                vl_[1][0] = r[2]; vl_[1][1] = r[3];
#pragma unroll
                for (int nt = 0; nt < 2; nt++) {
                    mma16816(O[2 * p + nt], ah, vh_[nt]);
                    mma16816(O[2 * p + nt], ah, vl_[nt]);
                    mma16816(O[2 * p + nt], al, vh_[nt]);
                }
            }
        }
    }

    // ---- normalize + write ctx split (bf16 hi/lo) ----
    const int h = bh & 15;
    const int b = bh >> 4;
    const float i0 = 1.f / l0, i1 = 1.f / l1;
    const int r0 = qtile * 128 + wid * 16 + (lane >> 2);
    const int colb = h * 64 + 2 * (lane & 3);
#pragma unroll
    for (int nt = 0; nt < 8; nt++) {
        const int col = colb + nt * 8;
#pragma unroll
        for (int half = 0; half < 2; half++) {
            float vx = O[nt][half * 2 + 0] * (half ? i1 : i0);
            float vy = O[nt][half * 2 + 1] * (half ? i1 : i0);
            size_t idx = ((size_t)b * SEQ + r0 + half * 8) * EMB + col;
            __nv_bfloat16 hx = __float2bfloat16_rn(vx);
            __nv_bfloat16 hy = __float2bfloat16_rn(vy);
            __nv_bfloat162 hv = {hx, hy};
            __nv_bfloat162 lv = {__float2bfloat16_rn(vx - __bfloat162float(hx)),
                                 __float2bfloat16_rn(vy - __bfloat162float(hy))};
            *(__nv_bfloat162*)(g_ch + idx) = hv;
            *(__nv_bfloat162*)(g_cl + idx) = lv;
        }
    }
}

// ---------------------------------------------------------------------------
extern "C" void kernel_launch(void* const* d_in, const int* in_sizes, int n_in,
                              void* d_out, int out_size) {
    (void)in_sizes; (void)n_in; (void)out_size;
    const float* x     = (const float*)d_in[0];
    const float* W_qkv = (const float*)d_in[1];
    const float* b_qkv = (const float*)d_in[2];
    const float* W_fc  = (const float*)d_in[3];
    const float* b_fc  = (const float*)d_in[4];
    float* out = (float*)d_out;

    // Pre-split inputs to bf16 hi/lo planes
    split_f32<<<(MROWS * EMB / 4 + 255) / 256, 256>>>(x, 0, MROWS * EMB / 4);
    split_f32<<<(EMB * 3072 / 4 + 255) / 256, 256>>>(W_qkv, 1, EMB * 3072 / 4);
    split_f32<<<(EMB * EMB / 4 + 255) / 256, 256>>>(W_fc, 2, EMB * EMB / 4);

    // QKV projection
    {
        cudaFuncSetAttribute(gemm_bf<0>, cudaFuncAttributeMaxDynamicSharedMemorySize, G2_TOTAL);
        dim3 grid(3072 / 128, MROWS / 128);
        gemm_bf<0><<<grid, 256, G2_TOTAL>>>(b_qkv, nullptr);
    }

    // Flash attention
    {
        cudaFuncSetAttribute(flash_attn_tc, cudaFuncAttributeMaxDynamicSharedMemorySize, FA_TOTAL);
        dim3 grid(SEQ / 128, BATCH * NHEAD);
        flash_attn_tc<<<grid, 256, FA_TOTAL>>>();
    }

    // Output projection
    {
        cudaFuncSetAttribute(gemm_bf<1>, cudaFuncAttributeMaxDynamicSharedMemorySize, G2_TOTAL);
        dim3 grid(1024 / 128, MROWS / 128);
        gemm_bf<1><<<grid, 256, G2_TOTAL>>>(b_fc, out);
    }
}

// round 13
// speedup vs baseline: 3.1596x; 1.0664x over previous
#include <cuda_runtime.h>
#include <cuda_bf16.h>
#include <math.h>
#include <stdint.h>

// Problem constants
#define BATCH   16
#define SEQ     1024
#define EMB     1024
#define NHEAD   16
#define DK      64
#define MROWS   (BATCH * SEQ)        // 16384

// Scratch (device globals; no allocation allowed)
__device__ __nv_bfloat16 g_xh[MROWS * EMB], g_xl[MROWS * EMB];
__device__ __nv_bfloat16 g_wqh[EMB * 3072], g_wql[EMB * 3072];
__device__ __nv_bfloat16 g_wfh[EMB * EMB],  g_wfl[EMB * EMB];
__device__ __nv_bfloat16 g_qh[BATCH * NHEAD * SEQ * DK], g_ql[BATCH * NHEAD * SEQ * DK];
__device__ __nv_bfloat16 g_kh[BATCH * NHEAD * SEQ * DK], g_kl[BATCH * NHEAD * SEQ * DK];
__device__ __nv_bfloat16 g_vh[BATCH * NHEAD * SEQ * DK], g_vl[BATCH * NHEAD * SEQ * DK];
__device__ __nv_bfloat16 g_ch[MROWS * EMB], g_cl[MROWS * EMB];

// ---------------------------------------------------------------------------
// PTX helpers
// ---------------------------------------------------------------------------
__device__ __forceinline__ uint32_t sm_u32(const void* p) {
    uint32_t a;
    asm("{ .reg .u64 t; cvta.to.shared.u64 t, %1; cvt.u32.u64 %0, t; }"
        : "=r"(a) : "l"(p));
    return a;
}
__device__ __forceinline__ void ldsm4(uint32_t addr, uint32_t* r) {
    asm volatile("ldmatrix.sync.aligned.m8n8.x4.shared.b16 {%0,%1,%2,%3}, [%4];"
                 : "=r"(r[0]), "=r"(r[1]), "=r"(r[2]), "=r"(r[3]) : "r"(addr));
}
__device__ __forceinline__ void ldsm4t(uint32_t addr, uint32_t* r) {
    asm volatile("ldmatrix.sync.aligned.m8n8.x4.trans.shared.b16 {%0,%1,%2,%3}, [%4];"
                 : "=r"(r[0]), "=r"(r[1]), "=r"(r[2]), "=r"(r[3]) : "r"(addr));
}
__device__ __forceinline__ void mma16816(float* d, const uint32_t* a, const uint32_t* b) {
    asm volatile(
        "mma.sync.aligned.m16n8k16.row.col.f32.bf16.bf16.f32 "
        "{%0,%1,%2,%3}, {%4,%5,%6,%7}, {%8,%9}, {%0,%1,%2,%3};"
        : "+f"(d[0]), "+f"(d[1]), "+f"(d[2]), "+f"(d[3])
        : "r"(a[0]), "r"(a[1]), "r"(a[2]), "r"(a[3]), "r"(b[0]), "r"(b[1]));
}
__device__ __forceinline__ void cpasync16(uint32_t dst, const void* src) {
    asm volatile("cp.async.cg.shared.global [%0], [%1], 16;" :: "r"(dst), "l"(src));
}
#define CP_COMMIT() asm volatile("cp.async.commit_group;" ::: "memory")
#define CP_WAIT(n)  asm volatile("cp.async.wait_group %0;" :: "n"(n) : "memory")

__device__ __forceinline__ uint32_t pack_bf2(float x, float y) {
    __nv_bfloat162 h = __floats2bfloat162_rn(x, y);
    return *(uint32_t*)&h;
}

// ---------------------------------------------------------------------------
// Pre-split: fp32 -> bf16 hi/lo planes.  which: 0=x 1=W_qkv 2=W_fc
// ---------------------------------------------------------------------------
__global__ __launch_bounds__(256) void split_f32(const float* __restrict__ src,
                                                 int which, int n4) {
    int i = blockIdx.x * 256 + threadIdx.x;
    if (i >= n4) return;
    __nv_bfloat16* hi = (which == 0) ? g_xh : (which == 1) ? g_wqh : g_wfh;
    __nv_bfloat16* lo = (which == 0) ? g_xl : (which == 1) ? g_wql : g_wfl;
    float4 v = __ldg((const float4*)src + i);
    __nv_bfloat162 h01 = __floats2bfloat162_rn(v.x, v.y);
    __nv_bfloat162 h23 = __floats2bfloat162_rn(v.z, v.w);
    __nv_bfloat162 l01 = __floats2bfloat162_rn(v.x - __bfloat162float(h01.x),
                                               v.y - __bfloat162float(h01.y));
    __nv_bfloat162 l23 = __floats2bfloat162_rn(v.z - __bfloat162float(h23.x),
                                               v.w - __bfloat162float(h23.y));
    *(uint2*)(hi + 4 * (size_t)i) = make_uint2(*(uint32_t*)&h01, *(uint32_t*)&h23);
    *(uint2*)(lo + 4 * (size_t)i) = make_uint2(*(uint32_t*)&l01, *(uint32_t*)&l23);
}

// ===========================================================================
// bf16-presplit GEMM: out[16384,N] = A @ W + bias.
// BK=64, 3-stage cp.async ring, ONE barrier per iteration.
// MODE 0: A=x-split, W=Wqkv-split (N=3072), scatter q/k/v hi/lo.
// MODE 1: A=ctx-split, W=Wfc-split (N=1024), fp32 out.
// ===========================================================================
#define SA_PITCH 144                // 64 bf16 = 128B + 16 pad (9x16B -> conflict-free)
#define SB_PITCH 272                // 128 bf16 = 256B + 16 pad (17x16B)
#define ST_AH 0
#define ST_AL (128 * SA_PITCH)              // 18432
#define ST_BH (2 * 128 * SA_PITCH)          // 36864
#define ST_BL (ST_BH + 64 * SB_PITCH)       // 54272
#define ST_SZ (ST_BL + 64 * SB_PITCH)       // 71680
#define G2_TOTAL (3 * ST_SZ)                // 215040

template <int MODE>
__global__ __launch_bounds__(256) void gemm_bf(const float* __restrict__ bias,
                                               float* __restrict__ out) {
    extern __shared__ char smem[];
    const uint32_t smb = sm_u32(smem);
    const int tid  = threadIdx.x;
    const int lane = tid & 31;
    const int wid  = tid >> 5;
    const int wm   = wid & 3;
    const int wn   = wid >> 2;
    const int mBase = blockIdx.y * 128;
    const int nBase = blockIdx.x * 128;
    const int ldW = (MODE == 0) ? 3072 : 1024;

    const __nv_bfloat16* Ah = (MODE == 0) ? g_xh : g_ch;
    const __nv_bfloat16* Al = (MODE == 0) ? g_xl : g_cl;
    const __nv_bfloat16* Bh = (MODE == 0) ? g_wqh : g_wfh;
    const __nv_bfloat16* Bl = (MODE == 0) ? g_wql : g_wfl;

    float acc[2][8][4];
#pragma unroll
    for (int i = 0; i < 2; i++)
#pragma unroll
        for (int j = 0; j < 8; j++)
#pragma unroll
            for (int q = 0; q < 4; q++) acc[i][j][q] = 0.f;

    // load one BK=64 stage: A 128x64 (hi+lo), B 64x128 (hi+lo)
    auto load_stage = [&](int stage, int kc) {
        const uint32_t sb = smb + stage * ST_SZ;
        const int kOff = kc * 64;
        // A: 128 rows x 8 x16B chunks x 2 planes = 2048 cp; 8/thread
#pragma unroll
        for (int i = 0; i < 4; i++) {
            int idx = tid + i * 256;                 // 0..1023
            int r = idx >> 3, ch = idx & 7;
            const size_t go = (size_t)(mBase + r) * 1024 + kOff + ch * 8;
            cpasync16(sb + ST_AH + r * SA_PITCH + ch * 16, Ah + go);
            cpasync16(sb + ST_AL + r * SA_PITCH + ch * 16, Al + go);
        }
        // B: 64 rows x 16 x16B chunks x 2 planes = 2048 cp; 8/thread
#pragma unroll
        for (int i = 0; i < 4; i++) {
            int idx = tid + i * 256;                 // 0..1023
            int r = idx >> 4, ch = idx & 15;
            const size_t go = (size_t)(kOff + r) * ldW + nBase + ch * 8;
            cpasync16(sb + ST_BH + r * SB_PITCH + ch * 16, Bh + go);
            cpasync16(sb + ST_BL + r * SB_PITCH + ch * 16, Bl + go);
        }
        CP_COMMIT();
    };

    load_stage(0, 0);
    load_stage(1, 1);

    for (int c = 0; c < 16; c++) {
        const int st = c % 3;
        if (c < 15) { CP_WAIT(1); } else { CP_WAIT(0); }
        __syncthreads();                 // stage st data visible to all; stage (c+2)%3 free
        if (c + 2 < 16) load_stage((c + 2) % 3, c + 2);

        const uint32_t sb = smb + st * ST_SZ;
#pragma unroll
        for (int ks = 0; ks < 4; ks++) {
            const int k0 = ks * 16;
            uint32_t Ahf[2][4], Alf[2][4];
#pragma unroll
            for (int mt = 0; mt < 2; mt++) {
                uint32_t addr = sb + (uint32_t)((wm * 32 + mt * 16 + (lane & 15)) * SA_PITCH
                                                + (k0 + (lane >> 4) * 8) * 2);
                ldsm4(addr + ST_AH, Ahf[mt]);
                ldsm4(addr + ST_AL, Alf[mt]);
            }
#pragma unroll
            for (int p = 0; p < 4; p++) {
                uint32_t addr = sb + (uint32_t)((k0 + (lane & 15)) * SB_PITCH
                                                + (wn * 64 + p * 16 + (lane >> 4) * 8) * 2);
                uint32_t r[4], bh_[2][2], bl_[2][2];
                ldsm4t(addr + ST_BH, r);
                bh_[0][0] = r[0]; bh_[0][1] = r[1];
                bh_[1][0] = r[2]; bh_[1][1] = r[3];
                ldsm4t(addr + ST_BL, r);
                bl_[0][0] = r[0]; bl_[0][1] = r[1];
                bl_[1][0] = r[2]; bl_[1][1] = r[3];
#pragma unroll
                for (int mt = 0; mt < 2; mt++)
#pragma unroll
                    for (int nt = 0; nt < 2; nt++) {
                        float* d = acc[mt][2 * p + nt];
                        mma16816(d, Ahf[mt], bh_[nt]);
                        mma16816(d, Ahf[mt], bl_[nt]);
                        mma16816(d, Alf[mt], bh_[nt]);
                    }
            }
        }
        // no trailing barrier: next iteration's barrier protects stage reuse
    }

    // ---- epilogue ----
    const int rbase = mBase + wm * 32 + (lane >> 2);
    const int cbase = nBase + wn * 64 + 2 * (lane & 3);
#pragma unroll
    for (int mt = 0; mt < 2; mt++) {
#pragma unroll
        for (int nt = 0; nt < 8; nt++) {
            const int col = cbase + nt * 8;
            const float bx = __ldg(&bias[col]);
            const float by = __ldg(&bias[col + 1]);
#pragma unroll
            for (int half = 0; half < 2; half++) {
                const int row = rbase + mt * 16 + half * 8;
                float vx = acc[mt][nt][half * 2 + 0] + bx;
                float vy = acc[mt][nt][half * 2 + 1] + by;
                if (MODE == 1) {
                    *(float2*)(out + (size_t)row * 1024 + col) = make_float2(vx, vy);
                } else {
                    const int which = col >> 10;
                    const int h = (col >> 6) & 15;
                    const int d0 = col & 63;
                    const int b = row >> 10;
                    const int n_tok = row & 1023;
                    size_t idx = ((size_t)(b * NHEAD + h) * SEQ + n_tok) * DK + d0;
                    __nv_bfloat16 hx = __float2bfloat16_rn(vx);
                    __nv_bfloat16 hy = __float2bfloat16_rn(vy);
                    __nv_bfloat162 hv = {hx, hy};
                    __nv_bfloat162 lv = {__float2bfloat16_rn(vx - __bfloat162float(hx)),
                                         __float2bfloat16_rn(vy - __bfloat162float(hy))};
                    __nv_bfloat16* dh = (which == 0) ? g_qh : (which == 1) ? g_kh : g_vh;
                    __nv_bfloat16* dl = (which == 0) ? g_ql : (which == 1) ? g_kl : g_vl;
                    *(__nv_bfloat162*)(dh + idx) = hv;
                    *(__nv_bfloat162*)(dl + idx) = lv;
                }
            }
        }
    }
}

// ===========================================================================
// Flash attention on tensor cores (unchanged from R8).
// ===========================================================================
#define FA_PITCH  144
#define FA_QH     0
#define FA_QL     (128 * FA_PITCH)
#define FA_KV0    (2 * 128 * FA_PITCH)
#define FA_KVSZ   (4 * 64 * FA_PITCH)
#define FA_KH     0
#define FA_KL     (64 * FA_PITCH)
#define FA_VH     (2 * 64 * FA_PITCH)
#define FA_VL     (3 * 64 * FA_PITCH)
#define FA_TOTAL  (FA_KV0 + 2 * FA_KVSZ)       // 110592

__global__ __launch_bounds__(256, 1) void flash_attn_tc() {
    extern __shared__ char smem[];
    const uint32_t smb = sm_u32(smem);
    const int tid  = threadIdx.x;
    const int lane = tid & 31;
    const int wid  = tid >> 5;
    const int qtile = blockIdx.x;
    const int bh    = blockIdx.y;

    const size_t headOff = (size_t)bh * SEQ * DK;
    const __nv_bfloat16* Qh = g_qh + headOff + (size_t)qtile * 128 * DK;
    const __nv_bfloat16* Ql = g_ql + headOff + (size_t)qtile * 128 * DK;

    {
#pragma unroll
        for (int i = 0; i < 4; i++) {
            int idx = tid + i * 256;
            int r = idx >> 3, c16 = idx & 7;
            cpasync16(smb + FA_QH + r * FA_PITCH + c16 * 16, (const char*)Qh + r * 128 + c16 * 16);
            cpasync16(smb + FA_QL + r * FA_PITCH + c16 * 16, (const char*)Ql + r * 128 + c16 * 16);
        }
        const __nv_bfloat16* src[4] = {g_kh + headOff, g_kl + headOff,
                                       g_vh + headOff, g_vl + headOff};
#pragma unroll
        for (int t4 = 0; t4 < 4; t4++) {
#pragma unroll
            for (int i = 0; i < 2; i++) {
                int idx = tid + i * 256;
                int r = idx >> 3, c16 = idx & 7;
                cpasync16(smb + FA_KV0 + t4 * (64 * FA_PITCH) + r * FA_PITCH + c16 * 16,
                          (const char*)src[t4] + r * 128 + c16 * 16);
            }
        }
        CP_COMMIT();
    }

    uint32_t QHf[4][4], QLf[4][4];
    float S[8][4];
    float O[8][4];
    float m0 = -INFINITY, m1 = -INFINITY, l0 = 0.f, l1 = 0.f;
#pragma unroll
    for (int nt = 0; nt < 8; nt++)
#pragma unroll
        for (int j = 0; j < 4; j++) O[nt][j] = 0.f;

    const __nv_bfloat16* Kh = g_kh + headOff;
    const __nv_bfloat16* Kl = g_kl + headOff;
    const __nv_bfloat16* Vh = g_vh + headOff;
    const __nv_bfloat16* Vl = g_vl + headOff;

    for (int c = 0; c < 16; c++) {
        const uint32_t kv = smb + FA_KV0 + (c & 1) * FA_KVSZ;

        if (c > 0) __syncthreads();

        if (c + 1 < 16) {
            const uint32_t nkv = smb + FA_KV0 + ((c + 1) & 1) * FA_KVSZ;
            const int rowOff = (c + 1) * 64;
            const __nv_bfloat16* src[4] = {Kh, Kl, Vh, Vl};
#pragma unroll
            for (int t4 = 0; t4 < 4; t4++) {
#pragma unroll
                for (int i = 0; i < 2; i++) {
                    int idx = tid + i * 256;
                    int r = idx >> 3, c16 = idx & 7;
                    cpasync16(nkv + t4 * (64 * FA_PITCH) + r * FA_PITCH + c16 * 16,
                              (const char*)src[t4] + (size_t)(rowOff + r) * 128 + c16 * 16);
                }
            }
            CP_COMMIT();
            CP_WAIT(1);
        } else {
            CP_WAIT(0);
        }
        __syncthreads();

        if (c == 0) {
#pragma unroll
            for (int ks = 0; ks < 4; ks++) {
                uint32_t addr = smb + (uint32_t)((wid * 16 + (lane & 15)) * FA_PITCH
                                                 + (ks * 16 + (lane >> 4) * 8) * 2);
                ldsm4(addr + FA_QH, QHf[ks]);
                ldsm4(addr + FA_QL, QLf[ks]);
            }
        }

#pragma unroll
        for (int nt = 0; nt < 8; nt++)
#pragma unroll
            for (int j = 0; j < 4; j++) S[nt][j] = 0.f;

#pragma unroll
        for (int p = 0; p < 4; p++) {
            uint32_t bh_[4][2][2], bl_[4][2][2];
#pragma unroll
            for (int ks = 0; ks < 4; ks++) {
                uint32_t addr = kv + (uint32_t)((p * 16 + (lane & 15)) * FA_PITCH
                                                + (ks * 16 + (lane >> 4) * 8) * 2);
                uint32_t r[4];
                ldsm4(addr + FA_KH, r);
                bh_[ks][0][0] = r[0]; bh_[ks][0][1] = r[2];
                bh_[ks][1][0] = r[1]; bh_[ks][1][1] = r[3];
                ldsm4(addr + FA_KL, r);
                bl_[ks][0][0] = r[0]; bl_[ks][0][1] = r[2];
                bl_[ks][1][0] = r[1]; bl_[ks][1][1] = r[3];
            }
#pragma unroll
            for (int ks = 0; ks < 4; ks++) {
#pragma unroll
                for (int nt = 0; nt < 2; nt++) {
                    mma16816(S[2 * p + nt], QHf[ks], bh_[ks][nt]);
                    mma16816(S[2 * p + nt], QHf[ks], bl_[ks][nt]);
                    mma16816(S[2 * p + nt], QLf[ks], bh_[ks][nt]);
                }
            }
        }

        float mx0 = -INFINITY, mx1 = -INFINITY;
#pragma unroll
        for (int nt = 0; nt < 8; nt++) {
            S[nt][0] *= 0.125f; S[nt][1] *= 0.125f;
            S[nt][2] *= 0.125f; S[nt][3] *= 0.125f;
            mx0 = fmaxf(mx0, fmaxf(S[nt][0], S[nt][1]));
            mx1 = fmaxf(mx1, fmaxf(S[nt][2], S[nt][3]));
        }
        mx0 = fmaxf(mx0, __shfl_xor_sync(0xffffffffu, mx0, 1));
        mx0 = fmaxf(mx0, __shfl_xor_sync(0xffffffffu, mx0, 2));
        mx1 = fmaxf(mx1, __shfl_xor_sync(0xffffffffu, mx1, 1));
        mx1 = fmaxf(mx1, __shfl_xor_sync(0xffffffffu, mx1, 2));
        const float nm0 = fmaxf(m0, mx0), nm1 = fmaxf(m1, mx1);
        const float a0 = __expf(m0 - nm0), a1 = __expf(m1 - nm1);
        m0 = nm0; m1 = nm1;
        float s0 = 0.f, s1 = 0.f;
#pragma unroll
        for (int nt = 0; nt < 8; nt++) {
            S[nt][0] = __expf(S[nt][0] - nm0);
            S[nt][1] = __expf(S[nt][1] - nm0);
            S[nt][2] = __expf(S[nt][2] - nm1);
            S[nt][3] = __expf(S[nt][3] - nm1);
            s0 += S[nt][0] + S[nt][1];
            s1 += S[nt][2] + S[nt][3];
        }
        s0 += __shfl_xor_sync(0xffffffffu, s0, 1);
        s0 += __shfl_xor_sync(0xffffffffu, s0, 2);
        s1 += __shfl_xor_sync(0xffffffffu, s1, 1);
        s1 += __shfl_xor_sync(0xffffffffu, s1, 2);
        l0 = l0 * a0 + s0;
        l1 = l1 * a1 + s1;
#pragma unroll
        for (int nt = 0; nt < 8; nt++) {
            O[nt][0] *= a0; O[nt][1] *= a0;
            O[nt][2] *= a1; O[nt][3] *= a1;
        }

#pragma unroll
        for (int kt = 0; kt < 4; kt++) {
            uint32_t ah[4], al[4];
            {
                float e0 = S[2 * kt][0], e1 = S[2 * kt][1];
                float e2 = S[2 * kt][2], e3 = S[2 * kt][3];
                float f0 = S[2 * kt + 1][0], f1 = S[2 * kt + 1][1];
                float f2 = S[2 * kt + 1][2], f3 = S[2 * kt + 1][3];
                ah[0] = pack_bf2(e0, e1); ah[1] = pack_bf2(e2, e3);
                ah[2] = pack_bf2(f0, f1); ah[3] = pack_bf2(f2, f3);
                __nv_bfloat162* hp;
                hp = (__nv_bfloat162*)&ah[0];
                al[0] = pack_bf2(e0 - __bfloat162float(hp->x), e1 - __bfloat162float(hp->y));
                hp = (__nv_bfloat162*)&ah[1];
                al[1] = pack_bf2(e2 - __bfloat162float(hp->x), e3 - __bfloat162float(hp->y));
                hp = (__nv_bfloat162*)&ah[2];
                al[2] = pack_bf2(f0 - __bfloat162float(hp->x), f1 - __bfloat162float(hp->y));
                hp = (__nv_bfloat162*)&ah[3];
                al[3] = pack_bf2(f2 - __bfloat162float(hp->x), f3 - __bfloat162float(hp->y));
            }
#pragma unroll
            for (int p = 0; p < 4; p++) {
                uint32_t addr = kv + (uint32_t)((kt * 16 + (lane & 15)) * FA_PITCH
                                                + (p * 16 + (lane >> 4) * 8) * 2);
                uint32_t r[4], vh_[2][2], vl_[2][2];
                ldsm4t(addr + FA_VH, r);
                vh_[0][0] = r[0]; vh_[0][1] = r[1];
                vh_[1][0] = r[2]; vh_[1][1] = r[3];
                ldsm4t(addr + FA_VL, r);
                vl_[0][0] = r[0]; vl_[0][1] = r[1];
                vl_[1][0] = r[2]; vl_[1][1] = r[3];
#pragma unroll
                for (int nt = 0; nt < 2; nt++) {
                    mma16816(O[2 * p + nt], ah, vh_[nt]);
                    mma16816(O[2 * p + nt], ah, vl_[nt]);
                    mma16816(O[2 * p + nt], al, vh_[nt]);
                }
            }
        }
    }

    const int h = bh & 15;
    const int b = bh >> 4;
    const float i0 = 1.f / l0, i1 = 1.f / l1;
    const int r0 = qtile * 128 + wid * 16 + (lane >> 2);
    const int colb = h * 64 + 2 * (lane & 3);
#pragma unroll
    for (int nt = 0; nt < 8; nt++) {
        const int col = colb + nt * 8;
#pragma unroll
        for (int half = 0; half < 2; half++) {
            float vx = O[nt][half * 2 + 0] * (half ? i1 : i0);
            float vy = O[nt][half * 2 + 1] * (half ? i1 : i0);
            size_t idx = ((size_t)b * SEQ + r0 + half * 8) * EMB + col;
            __nv_bfloat16 hx = __float2bfloat16_rn(vx);
            __nv_bfloat16 hy = __float2bfloat16_rn(vy);
            __nv_bfloat162 hv = {hx, hy};
            __nv_bfloat162 lv = {__float2bfloat16_rn(vx - __bfloat162float(hx)),
                                 __float2bfloat16_rn(vy - __bfloat162float(hy))};
            *(__nv_bfloat162*)(g_ch + idx) = hv;
            *(__nv_bfloat162*)(g_cl + idx) = lv;
        }
    }
}

// ---------------------------------------------------------------------------
extern "C" void kernel_launch(void* const* d_in, const int* in_sizes, int n_in,
                              void* d_out, int out_size) {
    (void)in_sizes; (void)n_in; (void)out_size;
    const float* x     = (const float*)d_in[0];
    const float* W_qkv = (const float*)d_in[1];
    const float* b_qkv = (const float*)d_in[2];
    const float* W_fc  = (const float*)d_in[3];
    const float* b_fc  = (const float*)d_in[4];
    float* out = (float*)d_out;

    split_f32<<<(MROWS * EMB / 4 + 255) / 256, 256>>>(x, 0, MROWS * EMB / 4);
    split_f32<<<(EMB * 3072 / 4 + 255) / 256, 256>>>(W_qkv, 1, EMB * 3072 / 4);
    split_f32<<<(EMB * EMB / 4 + 255) / 256, 256>>>(W_fc, 2, EMB * EMB / 4);

    {
        cudaFuncSetAttribute(gemm_bf<0>, cudaFuncAttributeMaxDynamicSharedMemorySize, G2_TOTAL);
        dim3 grid(3072 / 128, MROWS / 128);
        gemm_bf<0><<<grid, 256, G2_TOTAL>>>(b_qkv, nullptr);
    }
    {
        cudaFuncSetAttribute(flash_attn_tc, cudaFuncAttributeMaxDynamicSharedMemorySize, FA_TOTAL);
        dim3 grid(SEQ / 128, BATCH * NHEAD);
        flash_attn_tc<<<grid, 256, FA_TOTAL>>>();
    }
    {
        cudaFuncSetAttribute(gemm_bf<1>, cudaFuncAttributeMaxDynamicSharedMemorySize, G2_TOTAL);
        dim3 grid(1024 / 128, MROWS / 128);
        gemm_bf<1><<<grid, 256, G2_TOTAL>>>(b_fc, out);
    }
}